// round 13
// baseline (speedup 1.0000x reference)
#include <cuda_runtime.h>
#include <cuda_fp16.h>
#include <math.h>
#include <stdint.h>

typedef unsigned long long u64;

#define Bsz   1024
#define Pn    20
#define Ln    3
#define Tn    5
#define En    128
#define Nseq  (Bsz*Pn)          /* 20480 */
#define NPL   (Bsz*Pn*Ln)       /* 61440 */
#define NREL  60
#define DDOC  768
#define DENT  100
#define KPAD  112
#define MTOT  (NPL + 2*Bsz)     /* 63488 = 496*128 */

// ---------------- device scratch ----------------
__device__ __half g_AE [(size_t)MTOT * 128];
__device__ __half g_Bn [512 * 128];             // W_ih[:,0:128], PLAIN rows (for gemm smem path)
__device__ __half g_BhF[512 * 128];             // W_hh in mma-fragment order (global LDG path)
__device__ __half g_W1F[128 * 128];             // mlp_W1^T in mma-fragment order
__device__ __half g_Wec[128 * KPAD];
__device__ float  g_WTrel[128 * 512];           // f32 [k][c'] plain
__device__ __half g_relGb16[NREL * 512];        // [e][64 jp][i0,i1,f0,f1,g0,g1,o0,o1]
__device__ __half g_G16 [(size_t)MTOT * 512];   // [row][64 jp][8 gate-halves]

// ---- fast transcendentals ----
__device__ __forceinline__ float tanha(float x) {
    float y; asm("tanh.approx.f32 %0, %1;" : "=f"(y) : "f"(x)); return y;
}
__device__ __forceinline__ float siga(float x) {
    return fmaf(tanha(x * 0.5f), 0.5f, 0.5f);
}

// ---- f32x2 helpers ----
__device__ __forceinline__ u64 ffma2(u64 a, u64 b, u64 c) {
    u64 d; asm("fma.rn.f32x2 %0, %1, %2, %3;" : "=l"(d) : "l"(a), "l"(b), "l"(c)); return d;
}
__device__ __forceinline__ u64 dup2(float x) {
    u64 d; unsigned xi = __float_as_uint(x);
    asm("mov.b64 %0, {%1, %1};" : "=l"(d) : "r"(xi)); return d;
}
__device__ __forceinline__ float2 up2(u64 v) {
    unsigned lo, hi; asm("mov.b64 {%0, %1}, %2;" : "=r"(lo), "=r"(hi) : "l"(v));
    return make_float2(__uint_as_float(lo), __uint_as_float(hi));
}

// ---- mma / ldmatrix ----
__device__ __forceinline__ uint32_t s2u(const void* p) {
    uint32_t a;
    asm("{ .reg .u64 t; cvta.to.shared.u64 t, %1; cvt.u32.u64 %0, t; }" : "=r"(a) : "l"(p));
    return a;
}
__device__ __forceinline__ void ldmA(uint32_t* r, uint32_t addr) {
    asm volatile("ldmatrix.sync.aligned.m8n8.x4.shared.b16 {%0,%1,%2,%3}, [%4];"
                 : "=r"(r[0]), "=r"(r[1]), "=r"(r[2]), "=r"(r[3]) : "r"(addr));
}
__device__ __forceinline__ void ldmB(uint32_t* r, uint32_t addr) {
    asm volatile("ldmatrix.sync.aligned.m8n8.x2.shared.b16 {%0,%1}, [%2];"
                 : "=r"(r[0]), "=r"(r[1]) : "r"(addr));
}
__device__ __forceinline__ void mma16816(float* d, const uint32_t* a, const uint32_t* b) {
    asm volatile("mma.sync.aligned.m16n8k16.row.col.f32.f16.f16.f32 "
        "{%0,%1,%2,%3}, {%4,%5,%6,%7}, {%8,%9}, {%0,%1,%2,%3};"
        : "+f"(d[0]), "+f"(d[1]), "+f"(d[2]), "+f"(d[3])
        : "r"(a[0]), "r"(a[1]), "r"(a[2]), "r"(a[3]), "r"(b[0]), "r"(b[1]));
}

#define ASTR  272
#define CKSTR 240
#define DSTR  10
#define CSTR2 1040

// fragment-order half index for value B[c][k] (c = row, 128 k per row)
__device__ __forceinline__ int frag_idx(int c, int k) {
    int ntp = c >> 3, r = c & 7;
    int kp = k >> 5, ko = k & 31;
    int q = ko >> 3, t4v = (ko >> 1) & 3, o = ko & 1;
    int lane = r * 4 + t4v;
    return (((ntp * 4 + kp) * 32 + lane) * 4 + q) * 2 + o;
}

// ---------------- L0: news (blocks 0..255) + weight pack (blocks 256..767) ---------------
__global__ void k_news_transpose(const int* __restrict__ item1, const int* __restrict__ item2,
                                 const float* __restrict__ doc_table,
                                 const float* __restrict__ W1, const float* __restrict__ b1,
                                 const float* __restrict__ W2, const float* __restrict__ b2,
                                 const float* __restrict__ W_ih, const float* __restrict__ W_hh,
                                 const float* __restrict__ ec_W, const float* __restrict__ mlp_W1) {
    __shared__ __align__(16) float dsp[DDOC * DSTR];
    __shared__ __align__(16) float h1p[En * DSTR];
    __shared__ int items[8];
    int tid = threadIdx.x;

    if (blockIdx.x >= 256) {
        int idx = (blockIdx.x - 256) * 128 + tid;
        if (idx < 128 * KPAD) {
            int c = idx / KPAD, k = idx - c * KPAD;
            g_Wec[idx] = (k < DENT) ? __float2half_rn(ec_W[k * 128 + c]) : __half(0.0f);
        }
        if (idx < 128 * 128) {
            int n = idx >> 7, k = idx & 127;
            g_W1F[frag_idx(n, k)] = __float2half_rn(mlp_W1[k * 128 + n]);
        }
        int c = idx >> 7, k = idx & 127;   // plain row c = torch row
        g_Bn[idx] = __float2half_rn(W_ih[c * 256 + k]);
        g_BhF[frag_idx(c, k)] = __float2half_rn(W_hh[c * 128 + k]);
        g_WTrel[k * 512 + c] = W_ih[c * 256 + 128 + k];
        return;
    }

    int r0 = blockIdx.x * 8;
    if (tid < 8) {
        int row = r0 + tid;
        items[tid] = (row < Bsz) ? item1[row] : item2[row - Bsz];
    }
    __syncthreads();
    for (int k = tid; k < DDOC; k += 128) {
#pragma unroll
        for (int r = 0; r < 8; r++)
            dsp[k * DSTR + r] = doc_table[(size_t)items[r] * DDOC + k];
    }
    __syncthreads();
    u64 acc2[4];
    u64 bd = dup2(b1[tid]);
#pragma unroll
    for (int p = 0; p < 4; p++) acc2[p] = bd;
    for (int k = 0; k < DDOC; k++) {
        u64 wd = dup2(W1[k * En + tid]);
        const u64* hp = (const u64*)&dsp[k * DSTR];
#pragma unroll
        for (int p = 0; p < 4; p++) acc2[p] = ffma2(hp[p], wd, acc2[p]);
    }
#pragma unroll
    for (int p = 0; p < 4; p++) {
        float2 a = up2(acc2[p]);
        h1p[tid * DSTR + 2 * p]     = (a.x > 0.0f) ? a.x : expm1f(a.x);
        h1p[tid * DSTR + 2 * p + 1] = (a.y > 0.0f) ? a.y : expm1f(a.y);
    }
    __syncthreads();
    u64 bd2 = dup2(b2[tid]);
#pragma unroll
    for (int p = 0; p < 4; p++) acc2[p] = bd2;
    for (int k = 0; k < En; k++) {
        u64 wd = dup2(W2[k * En + tid]);
        const u64* hp = (const u64*)&h1p[k * DSTR];
#pragma unroll
        for (int p = 0; p < 4; p++) acc2[p] = ffma2(hp[p], wd, acc2[p]);
    }
#pragma unroll
    for (int p = 0; p < 4; p++) {
        float2 a = up2(acc2[p]);
        g_AE[(size_t)(NPL + r0 + 2 * p)     * En + tid] = __float2half_rn(tanhf(a.x));
        g_AE[(size_t)(NPL + r0 + 2 * p + 1) * En + tid] = __float2half_rn(tanhf(a.y));
    }
}

// ---------------- L1: entity compress (blocks 0..479) + relations (480..539) --------------
#define SMC_A 0
#define SMC_B (128 * CKSTR)
#define SMC_TOTAL (2 * 128 * CKSTR)
__global__ __launch_bounds__(512, 2) void k_compress_rel(const int* __restrict__ paths,
                                                         const float* __restrict__ ent_table,
                                                         const float* __restrict__ ec_b,
                                                         const float* __restrict__ rel_table,
                                                         const float* __restrict__ rc_W,
                                                         const float* __restrict__ rc_b,
                                                         const float* __restrict__ b_ih,
                                                         const float* __restrict__ b_hh) {
    extern __shared__ char sm[];
    __shared__ int spath[128];
    __shared__ float rr[DENT];
    __shared__ float rcs[En];
    int tid = threadIdx.x;

    if (blockIdx.x >= NPL / 128) {
        int rrow = blockIdx.x - NPL / 128;
        if (tid < DENT) rr[tid] = rel_table[rrow * DENT + tid];
        __syncthreads();
        if (tid < En) {
            float s = rc_b[tid];
            for (int k = 0; k < DENT; k++) s += rr[k] * rc_W[k * En + tid];
            rcs[tid] = tanhf(s);
        }
        __syncthreads();
        int c = tid;                       // plain: gate = c>>7, j = c&127
        int gate = c >> 7, j = c & 127;
        float s = b_ih[c] + b_hh[c];
        for (int k = 0; k < En; k++) s += rcs[k] * g_WTrel[k * 512 + c];
        g_relGb16[rrow * 512 + (j >> 1) * 8 + gate * 2 + (j & 1)] = __float2half_rn(s);
        return;
    }

    int w = tid >> 5, l = tid & 31;
    int wm = w & 3, wn = w >> 2;
    int row0 = blockIdx.x * 128;

    if (tid < 128) spath[tid] = paths[row0 + tid];
    __syncthreads();
    for (int idx = tid; idx < 128 * 25; idx += 512) {
        int r = idx / 25, k4 = idx - r * 25;
        float4 v = *(const float4*)(ent_table + (size_t)spath[r] * DENT + k4 * 4);
        uint2 u2;
        *((__half2*)&u2.x) = __floats2half2_rn(v.x, v.y);
        *((__half2*)&u2.y) = __floats2half2_rn(v.z, v.w);
        *(uint2*)(sm + SMC_A + r * CKSTR + k4 * 8) = u2;
    }
    for (int idx = tid; idx < 128 * 3; idx += 512) {
        int r = idx / 3, j = idx - r * 3;
        *(uint2*)(sm + SMC_A + r * CKSTR + 200 + j * 8) = make_uint2(0u, 0u);
    }
    for (int idx = tid; idx < 128 * 28; idx += 512) {
        int r = idx / 28, j = idx - r * 28;
        *(uint2*)(sm + SMC_B + r * CKSTR + j * 8) = ((const uint2*)g_Wec)[idx];
    }
    __syncthreads();

    uint32_t base = s2u(sm);
    int g8 = l & 7;
    uint32_t aBase = base + SMC_A + (uint32_t)(wm * 32 + g8 + ((l >> 3) & 1) * 8) * CKSTR
                   + ((l >> 4) & 1) * 16;
    uint32_t bBase = base + SMC_B + (uint32_t)(wn * 32 + g8) * CKSTR + ((l >> 3) & 1) * 16;

    float acc[2][4][4];
#pragma unroll
    for (int mt = 0; mt < 2; mt++)
#pragma unroll
        for (int nt = 0; nt < 4; nt++)
#pragma unroll
            for (int q = 0; q < 4; q++) acc[mt][nt][q] = 0.0f;

#pragma unroll
    for (int kt = 0; kt < 7; kt++) {
        uint32_t a[2][4];
        ldmA(a[0], aBase + kt * 32);
        ldmA(a[1], aBase + 16 * CKSTR + kt * 32);
#pragma unroll
        for (int nt = 0; nt < 4; nt++) {
            uint32_t b[2];
            ldmB(b, bBase + nt * 8 * CKSTR + kt * 32);
            mma16816(acc[0][nt], a[0], b);
            mma16816(acc[1][nt], a[1], b);
        }
    }
    __syncthreads();

    int tg = l & 3, gg = l >> 2;
#pragma unroll
    for (int mt = 0; mt < 2; mt++) {
        int r = wm * 32 + mt * 16 + gg;
#pragma unroll
        for (int nt = 0; nt < 4; nt++) {
            int cc = wn * 32 + nt * 8 + 2 * tg;
            float b0 = __ldg(ec_b + cc), b1 = __ldg(ec_b + cc + 1);
            *(__half2*)(sm + r * ASTR + cc * 2) =
                __floats2half2_rn(tanha(acc[mt][nt][0] + b0), tanha(acc[mt][nt][1] + b1));
            *(__half2*)(sm + (r + 8) * ASTR + cc * 2) =
                __floats2half2_rn(tanha(acc[mt][nt][2] + b0), tanha(acc[mt][nt][3] + b1));
        }
    }
    __syncthreads();
    for (int it = tid; it < 128 * 16; it += 512) {
        int r = it >> 4, bb = it & 15;
        uint4 v = *(uint4*)(sm + r * ASTR + bb * 16);
        *(uint4*)((char*)g_AE + (size_t)(row0 + r) * 256 + bb * 16) = v;
    }
}

// ---------------- L2: HMMA gate GEMM -> interleaved jp-records, full-row staging ----------
#define SMG_A 0
#define SMG_B (128 * ASTR)
#define SMG_C (2 * 128 * ASTR)
#define SMG_TOTAL (SMG_C + 128 * CSTR2)
__global__ __launch_bounds__(512, 1) void k_gemm_mma() {
    extern __shared__ char sm[];
    int tid = threadIdx.x, w = tid >> 5, l = tid & 31;
    int wm = w & 3, wn = w >> 2;
    int row0 = blockIdx.x * 128;

    const uint4* Ag = (const uint4*)g_AE;
    for (int idx = tid; idx < 128 * 16; idx += 512) {
        int r = idx >> 4, c4 = idx & 15;
        *(uint4*)(sm + SMG_A + r * ASTR + c4 * 16) = Ag[(size_t)(row0 + r) * 16 + c4];
    }

    uint32_t base = s2u(sm);
    int g8 = l & 7, tg = l & 3, gg = l >> 2;
    uint32_t aBase = base + SMG_A + (uint32_t)(wm * 32 + g8 + ((l >> 3) & 1) * 8) * ASTR
                   + ((l >> 4) & 1) * 16;
    uint32_t bBase = base + SMG_B + (uint32_t)(wn * 32 + g8) * ASTR + ((l >> 3) & 1) * 16;
    const uint4* Bg = (const uint4*)g_Bn;

    for (int nc = 0; nc < 4; nc++) {               // nc = gate
        __syncthreads();
        for (int idx = tid; idx < 128 * 16; idx += 512) {
            int n = idx >> 4, c4 = idx & 15;
            *(uint4*)(sm + SMG_B + n * ASTR + c4 * 16) = Bg[(size_t)(nc * 128 + n) * 16 + c4];
        }
        __syncthreads();

        float acc[2][4][4];
#pragma unroll
        for (int mt = 0; mt < 2; mt++)
#pragma unroll
            for (int nt = 0; nt < 4; nt++)
#pragma unroll
                for (int q = 0; q < 4; q++) acc[mt][nt][q] = 0.0f;

#pragma unroll
        for (int kt = 0; kt < 8; kt++) {
            uint32_t a[2][4];
            ldmA(a[0], aBase + kt * 32);
            ldmA(a[1], aBase + 16 * ASTR + kt * 32);
#pragma unroll
            for (int nt = 0; nt < 4; nt++) {
                uint32_t b[2];
                ldmB(b, bBase + nt * 8 * ASTR + kt * 32);
                mma16816(acc[0][nt], a[0], b);
                mma16816(acc[1][nt], a[1], b);
            }
        }
        __syncthreads();

#pragma unroll
        for (int mt = 0; mt < 2; mt++) {
            int r = wm * 32 + mt * 16 + gg;
#pragma unroll
            for (int nt = 0; nt < 4; nt++) {
                int jp = (wn * 4 + nt) * 4 + tg;
                *(__half2*)(sm + SMG_C + r * CSTR2 + jp * 16 + nc * 4) =
                    __floats2half2_rn(acc[mt][nt][0], acc[mt][nt][1]);
                *(__half2*)(sm + SMG_C + (r + 8) * CSTR2 + jp * 16 + nc * 4) =
                    __floats2half2_rn(acc[mt][nt][2], acc[mt][nt][3]);
            }
        }
    }
    __syncthreads();
    for (int it = tid; it < 128 * 64; it += 512) {
        int r = it >> 6, q = it & 63;
        uint4 v = *(uint4*)(sm + SMG_C + r * CSTR2 + q * 16);
        *(uint4*)((char*)g_G16 + (size_t)(row0 + r) * 1024 + q * 16) = v;
    }
}

// ---------------- L3: 1-warp-CTA LSTM, B fragments via global LDG (L1-resident) ----------
__global__ __launch_bounds__(32) void k_lstm_mma(const int* __restrict__ edges,
                                                 const float* __restrict__ mlp_b1,
                                                 const float* __restrict__ mlp_W2,
                                                 const float* __restrict__ mlp_b2,
                                                 float* __restrict__ scores_out) {
    int l = threadIdx.x;
    int gg = l >> 2, t4 = l & 3;
    int seqA = blockIdx.x * 16 + gg;
    int seqB = seqA + 8;
    int bA = seqA / Pn, bB = seqB / Pn;
    const uint4* BF = (const uint4*)g_BhF;
    const uint4* WF = (const uint4*)g_W1F;

    float cst[64];
#pragma unroll
    for (int q = 0; q < 64; q++) cst[q] = 0.0f;
    uint32_t hf[8][4];
#pragma unroll
    for (int kk = 0; kk < 8; kk++)
#pragma unroll
        for (int q = 0; q < 4; q++) hf[kk][q] = 0u;

    for (int t = 0; t < Tn; t++) {
        int rowGA = (t == 0) ? NPL + bA : (t == 4) ? NPL + Bsz + bA : seqA * Ln + (t - 1);
        int rowGB = (t == 0) ? NPL + bB : (t == 4) ? NPL + Bsz + bB : seqB * Ln + (t - 1);
        int eA = (t < Ln) ? edges[seqA * Ln + t] : 0;
        int eB = (t < Ln) ? edges[seqB * Ln + t] : 0;
        const char* gAr = (const char*)g_G16 + (size_t)rowGA * 1024 + t4 * 16;
        const char* gBr = (const char*)g_G16 + (size_t)rowGB * 1024 + t4 * 16;
        const char* rAr = (const char*)g_relGb16 + (size_t)eA * 1024 + t4 * 16;
        const char* rBr = (const char*)g_relGb16 + (size_t)eB * 1024 + t4 * 16;

        uint32_t hn[8][4];
#pragma unroll
        for (int kt = 0; kt < 8; kt++) {
#pragma unroll
            for (int half = 0; half < 2; half++) {
                int nt = kt * 2 + half;
                uint4 guA = *(const uint4*)(gAr + nt * 64);
                uint4 guB = *(const uint4*)(gBr + nt * 64);
                uint4 ruA = *(const uint4*)(rAr + nt * 64);
                uint4 ruB = *(const uint4*)(rBr + nt * 64);

                float acc[4][4];
#pragma unroll
                for (int g = 0; g < 4; g++)
#pragma unroll
                    for (int q = 0; q < 4; q++) acc[g][q] = 0.0f;
                if (t > 0) {
#pragma unroll
                    for (int kp = 0; kp < 4; kp++) {
#pragma unroll
                        for (int g = 0; g < 4; g++) {
                            uint4 v = __ldg(&BF[(size_t)(((g * 16 + nt) * 4 + kp) * 32 + l)]);
                            mma16816(acc[g], hf[2 * kp], (const uint32_t*)&v.x);
                            mma16816(acc[g], hf[2 * kp + 1], (const uint32_t*)&v.z);
                        }
                    }
                }
                float2 iA = __half22float2(*(const __half2*)&guA.x);
                float2 fA = __half22float2(*(const __half2*)&guA.y);
                float2 gA = __half22float2(*(const __half2*)&guA.z);
                float2 oA = __half22float2(*(const __half2*)&guA.w);
                float2 iB = __half22float2(*(const __half2*)&guB.x);
                float2 fB = __half22float2(*(const __half2*)&guB.y);
                float2 gB = __half22float2(*(const __half2*)&guB.z);
                float2 oB = __half22float2(*(const __half2*)&guB.w);
                float2 riA = __half22float2(*(const __half2*)&ruA.x);
                float2 rfA = __half22float2(*(const __half2*)&ruA.y);
                float2 rgA = __half22float2(*(const __half2*)&ruA.z);
                float2 roA = __half22float2(*(const __half2*)&ruA.w);
                float2 riB = __half22float2(*(const __half2*)&ruB.x);
                float2 rfB = __half22float2(*(const __half2*)&ruB.y);
                float2 rgB = __half22float2(*(const __half2*)&ruB.z);
                float2 roB = __half22float2(*(const __half2*)&ruB.w);

                int ci = nt * 4;
                float gi = acc[0][0] + iA.x + riA.x;
                float gf = acc[1][0] + fA.x + rfA.x;
                float gG = acc[2][0] + gA.x + rgA.x;
                float gO = acc[3][0] + oA.x + roA.x;
                cst[ci] = siga(gf) * cst[ci] + siga(gi) * tanha(gG);
                float hA0 = siga(gO) * tanha(cst[ci]);
                gi = acc[0][1] + iA.y + riA.y;
                gf = acc[1][1] + fA.y + rfA.y;
                gG = acc[2][1] + gA.y + rgA.y;
                gO = acc[3][1] + oA.y + roA.y;
                cst[ci + 1] = siga(gf) * cst[ci + 1] + siga(gi) * tanha(gG);
                float hA1 = siga(gO) * tanha(cst[ci + 1]);
                gi = acc[0][2] + iB.x + riB.x;
                gf = acc[1][2] + fB.x + rfB.x;
                gG = acc[2][2] + gB.x + rgB.x;
                gO = acc[3][2] + oB.x + roB.x;
                cst[ci + 2] = siga(gf) * cst[ci + 2] + siga(gi) * tanha(gG);
                float hB0 = siga(gO) * tanha(cst[ci + 2]);
                gi = acc[0][3] + iB.y + riB.y;
                gf = acc[1][3] + fB.y + rfB.y;
                gG = acc[2][3] + gB.y + rgB.y;
                gO = acc[3][3] + oB.y + roB.y;
                cst[ci + 3] = siga(gf) * cst[ci + 3] + siga(gi) * tanha(gG);
                float hB1 = siga(gO) * tanha(cst[ci + 3]);

                __half2 pA = __floats2half2_rn(hA0, hA1);
                __half2 pB = __floats2half2_rn(hB0, hB1);
                hn[kt][half * 2]     = *(uint32_t*)&pA;
                hn[kt][half * 2 + 1] = *(uint32_t*)&pB;
            }
        }
#pragma unroll
        for (int kk = 0; kk < 8; kk++)
#pragma unroll
            for (int q = 0; q < 4; q++) hf[kk][q] = hn[kk][q];
    }

    // ---- MLP via mma on register h-fragments (W1 fragments from global) ----
    float sc0 = 0.0f, sc1 = 0.0f;
#pragma unroll
    for (int ntg = 0; ntg < 16; ntg++) {
        float acc[4];
#pragma unroll
        for (int q = 0; q < 4; q++) acc[q] = 0.0f;
#pragma unroll
        for (int kp = 0; kp < 4; kp++) {
            uint4 v = __ldg(&WF[(size_t)((ntg * 4 + kp) * 32 + l)]);
            mma16816(acc, hf[2 * kp], (const uint32_t*)&v.x);
            mma16816(acc, hf[2 * kp + 1], (const uint32_t*)&v.z);
        }
        int j0 = ntg * 8 + t4 * 2;
        float b10 = __ldg(mlp_b1 + j0), b11 = __ldg(mlp_b1 + j0 + 1);
        float w20 = __ldg(mlp_W2 + j0), w21 = __ldg(mlp_W2 + j0 + 1);
        sc0 += fmaxf(acc[0] + b10, 0.0f) * w20 + fmaxf(acc[1] + b11, 0.0f) * w21;
        sc1 += fmaxf(acc[2] + b10, 0.0f) * w20 + fmaxf(acc[3] + b11, 0.0f) * w21;
    }
    sc0 += __shfl_xor_sync(0xffffffffu, sc0, 1);
    sc0 += __shfl_xor_sync(0xffffffffu, sc0, 2);
    sc1 += __shfl_xor_sync(0xffffffffu, sc1, 1);
    sc1 += __shfl_xor_sync(0xffffffffu, sc1, 2);
    if (t4 == 0) {
        float b2 = __ldg(mlp_b2);
        scores_out[seqA] = sc0 + b2;
        scores_out[seqB] = sc1 + b2;
    }
}

// ---------------- L4: logsumexp + BCE ----------------
__global__ void k_final(const float* __restrict__ label, float* __restrict__ out) {
    __shared__ float red[Bsz];
    int b = threadIdx.x;
    const float* sc = out + 1 + Bsz + b * Pn;
    float mx = -1e30f;
#pragma unroll
    for (int p = 0; p < Pn; p++) mx = fmaxf(mx, sc[p] * 0.5f);
    float s = 0.0f;
#pragma unroll
    for (int p = 0; p < Pn; p++) s += expf(sc[p] * 0.5f - mx);
    float lse = mx + logf(s);
    float pr = 1.0f / (1.0f + expf(-lse));
    out[1 + b] = pr;
    float pc = fminf(fmaxf(pr, 1e-7f), 1.0f - 1e-7f);
    float lb = label[b];
    red[b] = -(lb * logf(pc) + (1.0f - lb) * logf(1.0f - pc));
    __syncthreads();
    for (int st = Bsz / 2; st > 0; st >>= 1) {
        if (b < st) red[b] += red[b + st];
        __syncthreads();
    }
    if (b == 0) out[0] = red[0] / (float)Bsz;
}

// ---------------- launch ----------------
extern "C" void kernel_launch(void* const* d_in, const int* in_sizes, int n_in,
                              void* d_out, int out_size) {
    const int*   item1     = (const int*)d_in[0];
    const int*   item2     = (const int*)d_in[1];
    const int*   paths     = (const int*)d_in[2];
    const int*   edges     = (const int*)d_in[3];
    const float* label     = (const float*)d_in[4];
    const float* doc_table = (const float*)d_in[5];
    const float* ent_table = (const float*)d_in[6];
    const float* rel_table = (const float*)d_in[7];
    const float* nc_W1 = (const float*)d_in[8];
    const float* nc_b1 = (const float*)d_in[9];
    const float* nc_W2 = (const float*)d_in[10];
    const float* nc_b2 = (const float*)d_in[11];
    const float* ec_W  = (const float*)d_in[12];
    const float* ec_b  = (const float*)d_in[13];
    const float* rc_W  = (const float*)d_in[14];
    const float* rc_b  = (const float*)d_in[15];
    const float* W_ih  = (const float*)d_in[16];
    const float* W_hh  = (const float*)d_in[17];
    const float* b_ih  = (const float*)d_in[18];
    const float* b_hh  = (const float*)d_in[19];
    const float* mlp_W1 = (const float*)d_in[20];
    const float* mlp_b1 = (const float*)d_in[21];
    const float* mlp_W2 = (const float*)d_in[22];
    const float* mlp_b2 = (const float*)d_in[23];
    float* out = (float*)d_out;

    cudaFuncSetAttribute(k_compress_rel, cudaFuncAttributeMaxDynamicSharedMemorySize, SMC_TOTAL);
    cudaFuncSetAttribute(k_gemm_mma, cudaFuncAttributeMaxDynamicSharedMemorySize, SMG_TOTAL);

    k_news_transpose<<<768, 128>>>(item1, item2, doc_table, nc_W1, nc_b1, nc_W2, nc_b2,
                                   W_ih, W_hh, ec_W, mlp_W1);
    k_compress_rel<<<NPL / 128 + NREL, 512, SMC_TOTAL>>>(paths, ent_table, ec_b,
                                                         rel_table, rc_W, rc_b, b_ih, b_hh);
    k_gemm_mma<<<MTOT / 128, 512, SMG_TOTAL>>>();
    k_lstm_mma<<<Nseq / 16, 32>>>(edges, mlp_b1, mlp_W2, mlp_b2, out + 1 + Bsz);
    k_final<<<1, Bsz>>>(label, out);
}

// round 14
// speedup vs baseline: 1.1802x; 1.1802x over previous
#include <cuda_runtime.h>
#include <cuda_fp16.h>
#include <math.h>
#include <stdint.h>

typedef unsigned long long u64;

#define Bsz   1024
#define Pn    20
#define Ln    3
#define Tn    5
#define En    128
#define Nseq  (Bsz*Pn)          /* 20480 */
#define NPL   (Bsz*Pn*Ln)       /* 61440 */
#define NREL  60
#define DDOC  768
#define DENT  100
#define KPAD  112
#define MTOT  (NPL + 2*Bsz)     /* 63488 = 496*128 */

// ---------------- device scratch ----------------
__device__ __half g_AE [(size_t)MTOT * 128];
__device__ __half g_Bn [512 * 128];             // W_ih[:,0:128], PLAIN rows c'=gate*128+j
__device__ __half g_Bh [512 * 128];             // W_hh, PLAIN rows
__device__ __half g_W1h[128 * 128];             // mlp_W1^T f16: [n][k]
__device__ __half g_Wec[128 * KPAD];
__device__ float  g_WTrel[128 * 512];           // f32 [k][c'] plain
__device__ __half g_relGb16[NREL * 512];        // [e][64 jp][i0,i1,f0,f1,g0,g1,o0,o1]
__device__ __half g_G16 [(size_t)MTOT * 512];   // [row][64 jp][8 gate-halves]

// ---- fast transcendentals ----
__device__ __forceinline__ float tanha(float x) {
    float y; asm("tanh.approx.f32 %0, %1;" : "=f"(y) : "f"(x)); return y;
}
__device__ __forceinline__ float siga(float x) {
    return fmaf(tanha(x * 0.5f), 0.5f, 0.5f);
}

// ---- f32x2 helpers ----
__device__ __forceinline__ u64 ffma2(u64 a, u64 b, u64 c) {
    u64 d; asm("fma.rn.f32x2 %0, %1, %2, %3;" : "=l"(d) : "l"(a), "l"(b), "l"(c)); return d;
}
__device__ __forceinline__ u64 dup2(float x) {
    u64 d; unsigned xi = __float_as_uint(x);
    asm("mov.b64 %0, {%1, %1};" : "=l"(d) : "r"(xi)); return d;
}
__device__ __forceinline__ float2 up2(u64 v) {
    unsigned lo, hi; asm("mov.b64 {%0, %1}, %2;" : "=r"(lo), "=r"(hi) : "l"(v));
    return make_float2(__uint_as_float(lo), __uint_as_float(hi));
}

// ---- mma / ldmatrix ----
__device__ __forceinline__ uint32_t s2u(const void* p) {
    uint32_t a;
    asm("{ .reg .u64 t; cvta.to.shared.u64 t, %1; cvt.u32.u64 %0, t; }" : "=r"(a) : "l"(p));
    return a;
}
__device__ __forceinline__ void ldmA(uint32_t* r, uint32_t addr) {
    asm volatile("ldmatrix.sync.aligned.m8n8.x4.shared.b16 {%0,%1,%2,%3}, [%4];"
                 : "=r"(r[0]), "=r"(r[1]), "=r"(r[2]), "=r"(r[3]) : "r"(addr));
}
__device__ __forceinline__ void ldmB(uint32_t* r, uint32_t addr) {
    asm volatile("ldmatrix.sync.aligned.m8n8.x2.shared.b16 {%0,%1}, [%2];"
                 : "=r"(r[0]), "=r"(r[1]) : "r"(addr));
}
__device__ __forceinline__ void ldmB4(uint32_t* r, uint32_t addr) {
    asm volatile("ldmatrix.sync.aligned.m8n8.x4.shared.b16 {%0,%1,%2,%3}, [%4];"
                 : "=r"(r[0]), "=r"(r[1]), "=r"(r[2]), "=r"(r[3]) : "r"(addr));
}
__device__ __forceinline__ void mma16816(float* d, const uint32_t* a, const uint32_t* b) {
    asm volatile("mma.sync.aligned.m16n8k16.row.col.f32.f16.f16.f32 "
        "{%0,%1,%2,%3}, {%4,%5,%6,%7}, {%8,%9}, {%0,%1,%2,%3};"
        : "+f"(d[0]), "+f"(d[1]), "+f"(d[2]), "+f"(d[3])
        : "r"(a[0]), "r"(a[1]), "r"(a[2]), "r"(a[3]), "r"(b[0]), "r"(b[1]));
}

#define ASTR  272
#define CKSTR 240
#define DSTR  10
#define CSTR2 1040

// ---------------- L0: news (blocks 0..255) + weight pack (blocks 256..767) ---------------
__global__ void k_news_transpose(const int* __restrict__ item1, const int* __restrict__ item2,
                                 const float* __restrict__ doc_table,
                                 const float* __restrict__ W1, const float* __restrict__ b1,
                                 const float* __restrict__ W2, const float* __restrict__ b2,
                                 const float* __restrict__ W_ih, const float* __restrict__ W_hh,
                                 const float* __restrict__ ec_W, const float* __restrict__ mlp_W1) {
    __shared__ __align__(16) float dsp[DDOC * DSTR];
    __shared__ __align__(16) float h1p[En * DSTR];
    __shared__ int items[8];
    int tid = threadIdx.x;

    if (blockIdx.x >= 256) {
        int idx = (blockIdx.x - 256) * 128 + tid;
        if (idx < 128 * KPAD) {
            int c = idx / KPAD, k = idx - c * KPAD;
            g_Wec[idx] = (k < DENT) ? __float2half_rn(ec_W[k * 128 + c]) : __half(0.0f);
        }
        if (idx < 128 * 128) {
            int n = idx >> 7, k = idx & 127;
            g_W1h[idx] = __float2half_rn(mlp_W1[k * 128 + n]);
        }
        int c = idx >> 7, k = idx & 127;   // plain row c = torch row
        g_Bn[idx] = __float2half_rn(W_ih[c * 256 + k]);
        g_Bh[idx] = __float2half_rn(W_hh[c * 128 + k]);
        g_WTrel[k * 512 + c] = W_ih[c * 256 + 128 + k];
        return;
    }

    int r0 = blockIdx.x * 8;
    if (tid < 8) {
        int row = r0 + tid;
        items[tid] = (row < Bsz) ? item1[row] : item2[row - Bsz];
    }
    __syncthreads();
    for (int k = tid; k < DDOC; k += 128) {
#pragma unroll
        for (int r = 0; r < 8; r++)
            dsp[k * DSTR + r] = doc_table[(size_t)items[r] * DDOC + k];
    }
    __syncthreads();
    u64 acc2[4];
    u64 bd = dup2(b1[tid]);
#pragma unroll
    for (int p = 0; p < 4; p++) acc2[p] = bd;
    for (int k = 0; k < DDOC; k++) {
        u64 wd = dup2(W1[k * En + tid]);
        const u64* hp = (const u64*)&dsp[k * DSTR];
#pragma unroll
        for (int p = 0; p < 4; p++) acc2[p] = ffma2(hp[p], wd, acc2[p]);
    }
#pragma unroll
    for (int p = 0; p < 4; p++) {
        float2 a = up2(acc2[p]);
        h1p[tid * DSTR + 2 * p]     = (a.x > 0.0f) ? a.x : expm1f(a.x);
        h1p[tid * DSTR + 2 * p + 1] = (a.y > 0.0f) ? a.y : expm1f(a.y);
    }
    __syncthreads();
    u64 bd2 = dup2(b2[tid]);
#pragma unroll
    for (int p = 0; p < 4; p++) acc2[p] = bd2;
    for (int k = 0; k < En; k++) {
        u64 wd = dup2(W2[k * En + tid]);
        const u64* hp = (const u64*)&h1p[k * DSTR];
#pragma unroll
        for (int p = 0; p < 4; p++) acc2[p] = ffma2(hp[p], wd, acc2[p]);
    }
#pragma unroll
    for (int p = 0; p < 4; p++) {
        float2 a = up2(acc2[p]);
        g_AE[(size_t)(NPL + r0 + 2 * p)     * En + tid] = __float2half_rn(tanhf(a.x));
        g_AE[(size_t)(NPL + r0 + 2 * p + 1) * En + tid] = __float2half_rn(tanhf(a.y));
    }
}

// ---------------- L1: entity compress (blocks 0..479) + relations (480..539) --------------
#define SMC_A 0
#define SMC_B (128 * CKSTR)
#define SMC_TOTAL (2 * 128 * CKSTR)
__global__ __launch_bounds__(512, 2) void k_compress_rel(const int* __restrict__ paths,
                                                         const float* __restrict__ ent_table,
                                                         const float* __restrict__ ec_b,
                                                         const float* __restrict__ rel_table,
                                                         const float* __restrict__ rc_W,
                                                         const float* __restrict__ rc_b,
                                                         const float* __restrict__ b_ih,
                                                         const float* __restrict__ b_hh) {
    extern __shared__ char sm[];
    __shared__ int spath[128];
    __shared__ float rr[DENT];
    __shared__ float rcs[En];
    int tid = threadIdx.x;

    if (blockIdx.x >= NPL / 128) {
        int rrow = blockIdx.x - NPL / 128;
        if (tid < DENT) rr[tid] = rel_table[rrow * DENT + tid];
        __syncthreads();
        if (tid < En) {
            float s = rc_b[tid];
            for (int k = 0; k < DENT; k++) s += rr[k] * rc_W[k * En + tid];
            rcs[tid] = tanhf(s);
        }
        __syncthreads();
        int c = tid;                       // plain: gate = c>>7, j = c&127
        int gate = c >> 7, j = c & 127;
        float s = b_ih[c] + b_hh[c];
        for (int k = 0; k < En; k++) s += rcs[k] * g_WTrel[k * 512 + c];
        g_relGb16[rrow * 512 + (j >> 1) * 8 + gate * 2 + (j & 1)] = __float2half_rn(s);
        return;
    }

    int w = tid >> 5, l = tid & 31;
    int wm = w & 3, wn = w >> 2;
    int row0 = blockIdx.x * 128;

    if (tid < 128) spath[tid] = paths[row0 + tid];
    __syncthreads();
    for (int idx = tid; idx < 128 * 25; idx += 512) {
        int r = idx / 25, k4 = idx - r * 25;
        float4 v = *(const float4*)(ent_table + (size_t)spath[r] * DENT + k4 * 4);
        uint2 u2;
        *((__half2*)&u2.x) = __floats2half2_rn(v.x, v.y);
        *((__half2*)&u2.y) = __floats2half2_rn(v.z, v.w);
        *(uint2*)(sm + SMC_A + r * CKSTR + k4 * 8) = u2;
    }
    for (int idx = tid; idx < 128 * 3; idx += 512) {
        int r = idx / 3, j = idx - r * 3;
        *(uint2*)(sm + SMC_A + r * CKSTR + 200 + j * 8) = make_uint2(0u, 0u);
    }
    for (int idx = tid; idx < 128 * 28; idx += 512) {
        int r = idx / 28, j = idx - r * 28;
        *(uint2*)(sm + SMC_B + r * CKSTR + j * 8) = ((const uint2*)g_Wec)[idx];
    }
    __syncthreads();

    uint32_t base = s2u(sm);
    int g8 = l & 7;
    uint32_t aBase = base + SMC_A + (uint32_t)(wm * 32 + g8 + ((l >> 3) & 1) * 8) * CKSTR
                   + ((l >> 4) & 1) * 16;
    uint32_t bBase = base + SMC_B + (uint32_t)(wn * 32 + g8) * CKSTR + ((l >> 3) & 1) * 16;

    float acc[2][4][4];
#pragma unroll
    for (int mt = 0; mt < 2; mt++)
#pragma unroll
        for (int nt = 0; nt < 4; nt++)
#pragma unroll
            for (int q = 0; q < 4; q++) acc[mt][nt][q] = 0.0f;

#pragma unroll
    for (int kt = 0; kt < 7; kt++) {
        uint32_t a[2][4];
        ldmA(a[0], aBase + kt * 32);
        ldmA(a[1], aBase + 16 * CKSTR + kt * 32);
#pragma unroll
        for (int nt = 0; nt < 4; nt++) {
            uint32_t b[2];
            ldmB(b, bBase + nt * 8 * CKSTR + kt * 32);
            mma16816(acc[0][nt], a[0], b);
            mma16816(acc[1][nt], a[1], b);
        }
    }
    __syncthreads();

    int tg = l & 3, gg = l >> 2;
#pragma unroll
    for (int mt = 0; mt < 2; mt++) {
        int r = wm * 32 + mt * 16 + gg;
#pragma unroll
        for (int nt = 0; nt < 4; nt++) {
            int cc = wn * 32 + nt * 8 + 2 * tg;
            float b0 = __ldg(ec_b + cc), b1 = __ldg(ec_b + cc + 1);
            *(__half2*)(sm + r * ASTR + cc * 2) =
                __floats2half2_rn(tanha(acc[mt][nt][0] + b0), tanha(acc[mt][nt][1] + b1));
            *(__half2*)(sm + (r + 8) * ASTR + cc * 2) =
                __floats2half2_rn(tanha(acc[mt][nt][2] + b0), tanha(acc[mt][nt][3] + b1));
        }
    }
    __syncthreads();
    for (int it = tid; it < 128 * 16; it += 512) {
        int r = it >> 4, bb = it & 15;
        uint4 v = *(uint4*)(sm + r * ASTR + bb * 16);
        *(uint4*)((char*)g_AE + (size_t)(row0 + r) * 256 + bb * 16) = v;
    }
}

// ---------------- L2: HMMA gate GEMM -> interleaved jp-records, full-row staging ----------
#define SMG_A 0
#define SMG_B (128 * ASTR)
#define SMG_C (2 * 128 * ASTR)
#define SMG_TOTAL (SMG_C + 128 * CSTR2)
__global__ __launch_bounds__(512, 1) void k_gemm_mma() {
    extern __shared__ char sm[];
    int tid = threadIdx.x, w = tid >> 5, l = tid & 31;
    int wm = w & 3, wn = w >> 2;
    int row0 = blockIdx.x * 128;

    const uint4* Ag = (const uint4*)g_AE;
    for (int idx = tid; idx < 128 * 16; idx += 512) {
        int r = idx >> 4, c4 = idx & 15;
        *(uint4*)(sm + SMG_A + r * ASTR + c4 * 16) = Ag[(size_t)(row0 + r) * 16 + c4];
    }

    uint32_t base = s2u(sm);
    int g8 = l & 7, tg = l & 3, gg = l >> 2;
    uint32_t aBase = base + SMG_A + (uint32_t)(wm * 32 + g8 + ((l >> 3) & 1) * 8) * ASTR
                   + ((l >> 4) & 1) * 16;
    uint32_t bBase = base + SMG_B + (uint32_t)(wn * 32 + g8) * ASTR + ((l >> 3) & 1) * 16;
    const uint4* Bg = (const uint4*)g_Bn;

    for (int nc = 0; nc < 4; nc++) {               // nc = gate
        __syncthreads();
        for (int idx = tid; idx < 128 * 16; idx += 512) {
            int n = idx >> 4, c4 = idx & 15;
            *(uint4*)(sm + SMG_B + n * ASTR + c4 * 16) = Bg[(size_t)(nc * 128 + n) * 16 + c4];
        }
        __syncthreads();

        float acc[2][4][4];
#pragma unroll
        for (int mt = 0; mt < 2; mt++)
#pragma unroll
            for (int nt = 0; nt < 4; nt++)
#pragma unroll
                for (int q = 0; q < 4; q++) acc[mt][nt][q] = 0.0f;

#pragma unroll
        for (int kt = 0; kt < 8; kt++) {
            uint32_t a[2][4];
            ldmA(a[0], aBase + kt * 32);
            ldmA(a[1], aBase + 16 * ASTR + kt * 32);
#pragma unroll
            for (int nt = 0; nt < 4; nt++) {
                uint32_t b[2];
                ldmB(b, bBase + nt * 8 * ASTR + kt * 32);
                mma16816(acc[0][nt], a[0], b);
                mma16816(acc[1][nt], a[1], b);
            }
        }
        __syncthreads();

#pragma unroll
        for (int mt = 0; mt < 2; mt++) {
            int r = wm * 32 + mt * 16 + gg;
#pragma unroll
            for (int nt = 0; nt < 4; nt++) {
                int jp = (wn * 4 + nt) * 4 + tg;
                *(__half2*)(sm + SMG_C + r * CSTR2 + jp * 16 + nc * 4) =
                    __floats2half2_rn(acc[mt][nt][0], acc[mt][nt][1]);
                *(__half2*)(sm + SMG_C + (r + 8) * CSTR2 + jp * 16 + nc * 4) =
                    __floats2half2_rn(acc[mt][nt][2], acc[mt][nt][3]);
            }
        }
    }
    __syncthreads();
    for (int it = tid; it < 128 * 64; it += 512) {
        int r = it >> 6, q = it & 63;
        uint4 v = *(uint4*)(sm + SMG_C + r * CSTR2 + q * 16);
        *(uint4*)((char*)g_G16 + (size_t)(row0 + r) * 1024 + q * 16) = v;
    }
}

// ---------------- L3: barrier-free HMMA LSTM + mma MLP (10 warps, single wave) -----------
#define SL_B  0
#define SL_W1 (512 * ASTR)                        /* 139264 */
#define SL_TOTAL (SL_W1 + 128 * ASTR)             /* 174080 */
__global__ __launch_bounds__(320, 1) void k_lstm_mma(const int* __restrict__ edges,
                                                     const float* __restrict__ mlp_b1,
                                                     const float* __restrict__ mlp_W2,
                                                     const float* __restrict__ mlp_b2,
                                                     float* __restrict__ scores_out) {
    extern __shared__ char sm[];
    int tid = threadIdx.x, w = tid >> 5, l = tid & 31;

    const uint4* Bg = (const uint4*)g_Bh;
    for (int idx = tid; idx < 512 * 16; idx += 320) {
        int n = idx >> 4, c4 = idx & 15;
        *(uint4*)(sm + SL_B + n * ASTR + c4 * 16) = Bg[(size_t)n * 16 + c4];
    }
    const uint4* Wg = (const uint4*)g_W1h;
    for (int idx = tid; idx < 128 * 16; idx += 320) {
        int n = idx >> 4, c4 = idx & 15;
        *(uint4*)(sm + SL_W1 + n * ASTR + c4 * 16) = Wg[(size_t)n * 16 + c4];
    }
    __syncthreads();

    uint32_t base = s2u(sm);
    int g8 = l & 7, t4 = l & 3, gg = l >> 2;
    uint32_t bFrag = base + SL_B + (uint32_t)g8 * ASTR
                   + ((l >> 3) & 1) * 16 + ((l >> 4) & 1) * 32;
    uint32_t wFrag = base + SL_W1 + (uint32_t)g8 * ASTR
                   + ((l >> 3) & 1) * 16 + ((l >> 4) & 1) * 32;

    int seqA = blockIdx.x * 160 + w * 16 + gg;
    int seqB = seqA + 8;
    int bA = seqA / Pn, bB = seqB / Pn;

    float cst[64];
#pragma unroll
    for (int q = 0; q < 64; q++) cst[q] = 0.0f;
    uint32_t hf[8][4];
#pragma unroll
    for (int kk = 0; kk < 8; kk++)
#pragma unroll
        for (int q = 0; q < 4; q++) hf[kk][q] = 0u;

    for (int t = 0; t < Tn; t++) {
        int rowGA = (t == 0) ? NPL + bA : (t == 4) ? NPL + Bsz + bA : seqA * Ln + (t - 1);
        int rowGB = (t == 0) ? NPL + bB : (t == 4) ? NPL + Bsz + bB : seqB * Ln + (t - 1);
        int eA = (t < Ln) ? edges[seqA * Ln + t] : 0;
        int eB = (t < Ln) ? edges[seqB * Ln + t] : 0;
        const char* gAr = (const char*)g_G16 + (size_t)rowGA * 1024 + t4 * 16;
        const char* gBr = (const char*)g_G16 + (size_t)rowGB * 1024 + t4 * 16;
        const char* rAr = (const char*)g_relGb16 + (size_t)eA * 1024 + t4 * 16;
        const char* rBr = (const char*)g_relGb16 + (size_t)eB * 1024 + t4 * 16;

        uint32_t hn[8][4];
#pragma unroll
        for (int kt = 0; kt < 8; kt++) {
#pragma unroll
            for (int half = 0; half < 2; half++) {
                int nt = kt * 2 + half;
                uint4 guA = *(const uint4*)(gAr + nt * 64);
                uint4 guB = *(const uint4*)(gBr + nt * 64);
                uint4 ruA = *(const uint4*)(rAr + nt * 64);
                uint4 ruB = *(const uint4*)(rBr + nt * 64);

                float acc[4][4];
#pragma unroll
                for (int g = 0; g < 4; g++)
#pragma unroll
                    for (int q = 0; q < 4; q++) acc[g][q] = 0.0f;
                if (t > 0) {
                    uint32_t tRow = (uint32_t)(nt * 8) * ASTR;
#pragma unroll
                    for (int kp = 0; kp < 4; kp++) {
#pragma unroll
                        for (int g = 0; g < 4; g++) {
                            uint32_t b4[4];
                            ldmB4(b4, bFrag + tRow + (uint32_t)(g * 128) * ASTR + kp * 64);
                            mma16816(acc[g], hf[2 * kp], b4);
                            mma16816(acc[g], hf[2 * kp + 1], b4 + 2);
                        }
                    }
                }
                float2 iA = __half22float2(*(const __half2*)&guA.x);
                float2 fA = __half22float2(*(const __half2*)&guA.y);
                float2 gA = __half22float2(*(const __half2*)&guA.z);
                float2 oA = __half22float2(*(const __half2*)&guA.w);
                float2 iB = __half22float2(*(const __half2*)&guB.x);
                float2 fB = __half22float2(*(const __half2*)&guB.y);
                float2 gB = __half22float2(*(const __half2*)&guB.z);
                float2 oB = __half22float2(*(const __half2*)&guB.w);
                float2 riA = __half22float2(*(const __half2*)&ruA.x);
                float2 rfA = __half22float2(*(const __half2*)&ruA.y);
                float2 rgA = __half22float2(*(const __half2*)&ruA.z);
                float2 roA = __half22float2(*(const __half2*)&ruA.w);
                float2 riB = __half22float2(*(const __half2*)&ruB.x);
                float2 rfB = __half22float2(*(const __half2*)&ruB.y);
                float2 rgB = __half22float2(*(const __half2*)&ruB.z);
                float2 roB = __half22float2(*(const __half2*)&ruB.w);

                int ci = nt * 4;
                float gi = acc[0][0] + iA.x + riA.x;
                float gf = acc[1][0] + fA.x + rfA.x;
                float gG = acc[2][0] + gA.x + rgA.x;
                float gO = acc[3][0] + oA.x + roA.x;
                cst[ci] = siga(gf) * cst[ci] + siga(gi) * tanha(gG);
                float hA0 = siga(gO) * tanha(cst[ci]);
                gi = acc[0][1] + iA.y + riA.y;
                gf = acc[1][1] + fA.y + rfA.y;
                gG = acc[2][1] + gA.y + rgA.y;
                gO = acc[3][1] + oA.y + roA.y;
                cst[ci + 1] = siga(gf) * cst[ci + 1] + siga(gi) * tanha(gG);
                float hA1 = siga(gO) * tanha(cst[ci + 1]);
                gi = acc[0][2] + iB.x + riB.x;
                gf = acc[1][2] + fB.x + rfB.x;
                gG = acc[2][2] + gB.x + rgB.x;
                gO = acc[3][2] + oB.x + roB.x;
                cst[ci + 2] = siga(gf) * cst[ci + 2] + siga(gi) * tanha(gG);
                float hB0 = siga(gO) * tanha(cst[ci + 2]);
                gi = acc[0][3] + iB.y + riB.y;
                gf = acc[1][3] + fB.y + rfB.y;
                gG = acc[2][3] + gB.y + rgB.y;
                gO = acc[3][3] + oB.y + roB.y;
                cst[ci + 3] = siga(gf) * cst[ci + 3] + siga(gi) * tanha(gG);
                float hB1 = siga(gO) * tanha(cst[ci + 3]);

                __half2 pA = __floats2half2_rn(hA0, hA1);
                __half2 pB = __floats2half2_rn(hB0, hB1);
                hn[kt][half * 2]     = *(uint32_t*)&pA;
                hn[kt][half * 2 + 1] = *(uint32_t*)&pB;
            }
        }
#pragma unroll
        for (int kk = 0; kk < 8; kk++)
#pragma unroll
            for (int q = 0; q < 4; q++) hf[kk][q] = hn[kk][q];
    }

    // ---- MLP via mma on register h-fragments (W1 fragments from smem) ----
    float sc0 = 0.0f, sc1 = 0.0f;
#pragma unroll
    for (int ntg = 0; ntg < 16; ntg++) {
        float acc[4];
#pragma unroll
        for (int q = 0; q < 4; q++) acc[q] = 0.0f;
        uint32_t tRow = (uint32_t)(ntg * 8) * ASTR;
#pragma unroll
        for (int kp = 0; kp < 4; kp++) {
            uint32_t b4[4];
            ldmB4(b4, wFrag + tRow + kp * 64);
            mma16816(acc, hf[2 * kp], b4);
            mma16816(acc, hf[2 * kp + 1], b4 + 2);
        }
        int j0 = ntg * 8 + t4 * 2;
        float b10 = __ldg(mlp_b1 + j0), b11 = __ldg(mlp_b1 + j0 + 1);
        float w20 = __ldg(mlp_W2 + j0), w21 = __ldg(mlp_W2 + j0 + 1);
        sc0 += fmaxf(acc[0] + b10, 0.0f) * w20 + fmaxf(acc[1] + b11, 0.0f) * w21;
        sc1 += fmaxf(acc[2] + b10, 0.0f) * w20 + fmaxf(acc[3] + b11, 0.0f) * w21;
    }
    sc0 += __shfl_xor_sync(0xffffffffu, sc0, 1);
    sc0 += __shfl_xor_sync(0xffffffffu, sc0, 2);
    sc1 += __shfl_xor_sync(0xffffffffu, sc1, 1);
    sc1 += __shfl_xor_sync(0xffffffffu, sc1, 2);
    if (t4 == 0) {
        float b2 = __ldg(mlp_b2);
        scores_out[seqA] = sc0 + b2;
        scores_out[seqB] = sc1 + b2;
    }
}

// ---------------- L4: logsumexp + BCE ----------------
__global__ void k_final(const float* __restrict__ label, float* __restrict__ out) {
    __shared__ float red[Bsz];
    int b = threadIdx.x;
    const float* sc = out + 1 + Bsz + b * Pn;
    float mx = -1e30f;
#pragma unroll
    for (int p = 0; p < Pn; p++) mx = fmaxf(mx, sc[p] * 0.5f);
    float s = 0.0f;
#pragma unroll
    for (int p = 0; p < Pn; p++) s += expf(sc[p] * 0.5f - mx);
    float lse = mx + logf(s);
    float pr = 1.0f / (1.0f + expf(-lse));
    out[1 + b] = pr;
    float pc = fminf(fmaxf(pr, 1e-7f), 1.0f - 1e-7f);
    float lb = label[b];
    red[b] = -(lb * logf(pc) + (1.0f - lb) * logf(1.0f - pc));
    __syncthreads();
    for (int st = Bsz / 2; st > 0; st >>= 1) {
        if (b < st) red[b] += red[b + st];
        __syncthreads();
    }
    if (b == 0) out[0] = red[0] / (float)Bsz;
}

// ---------------- launch ----------------
extern "C" void kernel_launch(void* const* d_in, const int* in_sizes, int n_in,
                              void* d_out, int out_size) {
    const int*   item1     = (const int*)d_in[0];
    const int*   item2     = (const int*)d_in[1];
    const int*   paths     = (const int*)d_in[2];
    const int*   edges     = (const int*)d_in[3];
    const float* label     = (const float*)d_in[4];
    const float* doc_table = (const float*)d_in[5];
    const float* ent_table = (const float*)d_in[6];
    const float* rel_table = (const float*)d_in[7];
    const float* nc_W1 = (const float*)d_in[8];
    const float* nc_b1 = (const float*)d_in[9];
    const float* nc_W2 = (const float*)d_in[10];
    const float* nc_b2 = (const float*)d_in[11];
    const float* ec_W  = (const float*)d_in[12];
    const float* ec_b  = (const float*)d_in[13];
    const float* rc_W  = (const float*)d_in[14];
    const float* rc_b  = (const float*)d_in[15];
    const float* W_ih  = (const float*)d_in[16];
    const float* W_hh  = (const float*)d_in[17];
    const float* b_ih  = (const float*)d_in[18];
    const float* b_hh  = (const float*)d_in[19];
    const float* mlp_W1 = (const float*)d_in[20];
    const float* mlp_b1 = (const float*)d_in[21];
    const float* mlp_W2 = (const float*)d_in[22];
    const float* mlp_b2 = (const float*)d_in[23];
    float* out = (float*)d_out;

    cudaFuncSetAttribute(k_compress_rel, cudaFuncAttributeMaxDynamicSharedMemorySize, SMC_TOTAL);
    cudaFuncSetAttribute(k_gemm_mma, cudaFuncAttributeMaxDynamicSharedMemorySize, SMG_TOTAL);
    cudaFuncSetAttribute(k_lstm_mma, cudaFuncAttributeMaxDynamicSharedMemorySize, SL_TOTAL);

    k_news_transpose<<<768, 128>>>(item1, item2, doc_table, nc_W1, nc_b1, nc_W2, nc_b2,
                                   W_ih, W_hh, ec_W, mlp_W1);
    k_compress_rel<<<NPL / 128 + NREL, 512, SMC_TOTAL>>>(paths, ent_table, ec_b,
                                                         rel_table, rc_W, rc_b, b_ih, b_hh);
    k_gemm_mma<<<MTOT / 128, 512, SMG_TOTAL>>>();
    k_lstm_mma<<<Nseq / 160, 320, SL_TOTAL>>>(edges, mlp_b1, mlp_W2, mlp_b2, out + 1 + Bsz);
    k_final<<<1, Bsz>>>(label, out);
}

// round 15
// speedup vs baseline: 1.2250x; 1.0380x over previous
#include <cuda_runtime.h>
#include <cuda_fp16.h>
#include <math.h>
#include <stdint.h>

typedef unsigned long long u64;

#define Bsz   1024
#define Pn    20
#define Ln    3
#define Tn    5
#define En    128
#define Nseq  (Bsz*Pn)          /* 20480 */
#define NPL   (Bsz*Pn*Ln)       /* 61440 */
#define NREL  60
#define DDOC  768
#define DENT  100
#define KPAD  112
#define MTOT  (NPL + 2*Bsz)     /* 63488 = 496*128 */

// ---------------- device scratch ----------------
__device__ __half g_AE [(size_t)MTOT * 128];
__device__ __half g_Bn [512 * 128];             // W_ih[:,0:128], rows reordered: (j>>5)*128+gate*32+(j&31)
__device__ __half g_Bh [512 * 128];             // W_hh, PLAIN rows
__device__ __half g_W1h[128 * 128];             // mlp_W1^T f16: [n][k]
__device__ __half g_Wec[128 * KPAD];
__device__ float  g_WTrel[128 * 512];           // f32 [k][c'] plain
__device__ __half g_relGb16[NREL * 512];        // [e][64 jp][i0,i1,f0,f1,g0,g1,o0,o1]
__device__ __half g_G16 [(size_t)MTOT * 512];   // [row][64 jp][8 gate-halves]

// ---- fast transcendentals ----
__device__ __forceinline__ float tanha(float x) {
    float y; asm("tanh.approx.f32 %0, %1;" : "=f"(y) : "f"(x)); return y;
}
__device__ __forceinline__ float siga(float x) {
    return fmaf(tanha(x * 0.5f), 0.5f, 0.5f);
}

// ---- f32x2 helpers ----
__device__ __forceinline__ u64 ffma2(u64 a, u64 b, u64 c) {
    u64 d; asm("fma.rn.f32x2 %0, %1, %2, %3;" : "=l"(d) : "l"(a), "l"(b), "l"(c)); return d;
}
__device__ __forceinline__ u64 dup2(float x) {
    u64 d; unsigned xi = __float_as_uint(x);
    asm("mov.b64 %0, {%1, %1};" : "=l"(d) : "r"(xi)); return d;
}
__device__ __forceinline__ float2 up2(u64 v) {
    unsigned lo, hi; asm("mov.b64 {%0, %1}, %2;" : "=r"(lo), "=r"(hi) : "l"(v));
    return make_float2(__uint_as_float(lo), __uint_as_float(hi));
}

// ---- mma / ldmatrix ----
__device__ __forceinline__ uint32_t s2u(const void* p) {
    uint32_t a;
    asm("{ .reg .u64 t; cvta.to.shared.u64 t, %1; cvt.u32.u64 %0, t; }" : "=r"(a) : "l"(p));
    return a;
}
__device__ __forceinline__ void ldmA(uint32_t* r, uint32_t addr) {
    asm volatile("ldmatrix.sync.aligned.m8n8.x4.shared.b16 {%0,%1,%2,%3}, [%4];"
                 : "=r"(r[0]), "=r"(r[1]), "=r"(r[2]), "=r"(r[3]) : "r"(addr));
}
__device__ __forceinline__ void ldmB(uint32_t* r, uint32_t addr) {
    asm volatile("ldmatrix.sync.aligned.m8n8.x2.shared.b16 {%0,%1}, [%2];"
                 : "=r"(r[0]), "=r"(r[1]) : "r"(addr));
}
__device__ __forceinline__ void ldmB4(uint32_t* r, uint32_t addr) {
    asm volatile("ldmatrix.sync.aligned.m8n8.x4.shared.b16 {%0,%1,%2,%3}, [%4];"
                 : "=r"(r[0]), "=r"(r[1]), "=r"(r[2]), "=r"(r[3]) : "r"(addr));
}
__device__ __forceinline__ void mma16816(float* d, const uint32_t* a, const uint32_t* b) {
    asm volatile("mma.sync.aligned.m16n8k16.row.col.f32.f16.f16.f32 "
        "{%0,%1,%2,%3}, {%4,%5,%6,%7}, {%8,%9}, {%0,%1,%2,%3};"
        : "+f"(d[0]), "+f"(d[1]), "+f"(d[2]), "+f"(d[3])
        : "r"(a[0]), "r"(a[1]), "r"(a[2]), "r"(a[3]), "r"(b[0]), "r"(b[1]));
}

#define ASTR  272
#define CKSTR 240
#define DSTR  10

// ---------------- L0: news (blocks 0..255) + weight pack (blocks 256..767) ---------------
__global__ void k_news_transpose(const int* __restrict__ item1, const int* __restrict__ item2,
                                 const float* __restrict__ doc_table,
                                 const float* __restrict__ W1, const float* __restrict__ b1,
                                 const float* __restrict__ W2, const float* __restrict__ b2,
                                 const float* __restrict__ W_ih, const float* __restrict__ W_hh,
                                 const float* __restrict__ ec_W, const float* __restrict__ mlp_W1) {
    __shared__ __align__(16) float dsp[DDOC * DSTR];
    __shared__ __align__(16) float h1p[En * DSTR];
    __shared__ int items[8];
    int tid = threadIdx.x;

    if (blockIdx.x >= 256) {
        int idx = (blockIdx.x - 256) * 128 + tid;
        if (idx < 128 * KPAD) {
            int c = idx / KPAD, k = idx - c * KPAD;
            g_Wec[idx] = (k < DENT) ? __float2half_rn(ec_W[k * 128 + c]) : __half(0.0f);
        }
        if (idx < 128 * 128) {
            int n = idx >> 7, k = idx & 127;
            g_W1h[idx] = __float2half_rn(mlp_W1[k * 128 + n]);
        }
        int c = idx >> 7, k = idx & 127;   // c = torch row = gate*128 + j
        int gate = c >> 7, j = c & 127;
        int c2 = (j >> 5) * 128 + gate * 32 + (j & 31);   // j-chunk-major reorder
        g_Bn[c2 * 128 + k] = __float2half_rn(W_ih[c * 256 + k]);
        g_Bh[idx] = __float2half_rn(W_hh[c * 128 + k]);
        g_WTrel[k * 512 + c] = W_ih[c * 256 + 128 + k];
        return;
    }

    int r0 = blockIdx.x * 8;
    if (tid < 8) {
        int row = r0 + tid;
        items[tid] = (row < Bsz) ? item1[row] : item2[row - Bsz];
    }
    __syncthreads();
    for (int k = tid; k < DDOC; k += 128) {
#pragma unroll
        for (int r = 0; r < 8; r++)
            dsp[k * DSTR + r] = doc_table[(size_t)items[r] * DDOC + k];
    }
    __syncthreads();
    u64 acc2[4];
    u64 bd = dup2(b1[tid]);
#pragma unroll
    for (int p = 0; p < 4; p++) acc2[p] = bd;
    for (int k = 0; k < DDOC; k++) {
        u64 wd = dup2(W1[k * En + tid]);
        const u64* hp = (const u64*)&dsp[k * DSTR];
#pragma unroll
        for (int p = 0; p < 4; p++) acc2[p] = ffma2(hp[p], wd, acc2[p]);
    }
#pragma unroll
    for (int p = 0; p < 4; p++) {
        float2 a = up2(acc2[p]);
        h1p[tid * DSTR + 2 * p]     = (a.x > 0.0f) ? a.x : expm1f(a.x);
        h1p[tid * DSTR + 2 * p + 1] = (a.y > 0.0f) ? a.y : expm1f(a.y);
    }
    __syncthreads();
    u64 bd2 = dup2(b2[tid]);
#pragma unroll
    for (int p = 0; p < 4; p++) acc2[p] = bd2;
    for (int k = 0; k < En; k++) {
        u64 wd = dup2(W2[k * En + tid]);
        const u64* hp = (const u64*)&h1p[k * DSTR];
#pragma unroll
        for (int p = 0; p < 4; p++) acc2[p] = ffma2(hp[p], wd, acc2[p]);
    }
#pragma unroll
    for (int p = 0; p < 4; p++) {
        float2 a = up2(acc2[p]);
        g_AE[(size_t)(NPL + r0 + 2 * p)     * En + tid] = __float2half_rn(tanhf(a.x));
        g_AE[(size_t)(NPL + r0 + 2 * p + 1) * En + tid] = __float2half_rn(tanhf(a.y));
    }
}

// ---------------- L1: entity compress (blocks 0..479) + relations (480..539) --------------
#define SMC_A 0
#define SMC_B (128 * CKSTR)
#define SMC_TOTAL (2 * 128 * CKSTR)
__global__ __launch_bounds__(512, 2) void k_compress_rel(const int* __restrict__ paths,
                                                         const float* __restrict__ ent_table,
                                                         const float* __restrict__ ec_b,
                                                         const float* __restrict__ rel_table,
                                                         const float* __restrict__ rc_W,
                                                         const float* __restrict__ rc_b,
                                                         const float* __restrict__ b_ih,
                                                         const float* __restrict__ b_hh) {
    extern __shared__ char sm[];
    __shared__ int spath[128];
    __shared__ float rr[DENT];
    __shared__ float rcs[En];
    int tid = threadIdx.x;

    if (blockIdx.x >= NPL / 128) {
        int rrow = blockIdx.x - NPL / 128;
        if (tid < DENT) rr[tid] = rel_table[rrow * DENT + tid];
        __syncthreads();
        if (tid < En) {
            float s = rc_b[tid];
            for (int k = 0; k < DENT; k++) s += rr[k] * rc_W[k * En + tid];
            rcs[tid] = tanhf(s);
        }
        __syncthreads();
        int c = tid;
        int gate = c >> 7, j = c & 127;
        float s = b_ih[c] + b_hh[c];
        for (int k = 0; k < En; k++) s += rcs[k] * g_WTrel[k * 512 + c];
        g_relGb16[rrow * 512 + (j >> 1) * 8 + gate * 2 + (j & 1)] = __float2half_rn(s);
        return;
    }

    int w = tid >> 5, l = tid & 31;
    int wm = w & 3, wn = w >> 2;
    int row0 = blockIdx.x * 128;

    if (tid < 128) spath[tid] = paths[row0 + tid];
    __syncthreads();
    for (int idx = tid; idx < 128 * 25; idx += 512) {
        int r = idx / 25, k4 = idx - r * 25;
        float4 v = *(const float4*)(ent_table + (size_t)spath[r] * DENT + k4 * 4);
        uint2 u2;
        *((__half2*)&u2.x) = __floats2half2_rn(v.x, v.y);
        *((__half2*)&u2.y) = __floats2half2_rn(v.z, v.w);
        *(uint2*)(sm + SMC_A + r * CKSTR + k4 * 8) = u2;
    }
    for (int idx = tid; idx < 128 * 3; idx += 512) {
        int r = idx / 3, j = idx - r * 3;
        *(uint2*)(sm + SMC_A + r * CKSTR + 200 + j * 8) = make_uint2(0u, 0u);
    }
    for (int idx = tid; idx < 128 * 28; idx += 512) {
        int r = idx / 28, j = idx - r * 28;
        *(uint2*)(sm + SMC_B + r * CKSTR + j * 8) = ((const uint2*)g_Wec)[idx];
    }
    __syncthreads();

    uint32_t base = s2u(sm);
    int g8 = l & 7;
    uint32_t aBase = base + SMC_A + (uint32_t)(wm * 32 + g8 + ((l >> 3) & 1) * 8) * CKSTR
                   + ((l >> 4) & 1) * 16;
    uint32_t bBase = base + SMC_B + (uint32_t)(wn * 32 + g8) * CKSTR + ((l >> 3) & 1) * 16;

    float acc[2][4][4];
#pragma unroll
    for (int mt = 0; mt < 2; mt++)
#pragma unroll
        for (int nt = 0; nt < 4; nt++)
#pragma unroll
            for (int q = 0; q < 4; q++) acc[mt][nt][q] = 0.0f;

#pragma unroll
    for (int kt = 0; kt < 7; kt++) {
        uint32_t a[2][4];
        ldmA(a[0], aBase + kt * 32);
        ldmA(a[1], aBase + 16 * CKSTR + kt * 32);
#pragma unroll
        for (int nt = 0; nt < 4; nt++) {
            uint32_t b[2];
            ldmB(b, bBase + nt * 8 * CKSTR + kt * 32);
            mma16816(acc[0][nt], a[0], b);
            mma16816(acc[1][nt], a[1], b);
        }
    }
    __syncthreads();

    int tg = l & 3, gg = l >> 2;
#pragma unroll
    for (int mt = 0; mt < 2; mt++) {
        int r = wm * 32 + mt * 16 + gg;
#pragma unroll
        for (int nt = 0; nt < 4; nt++) {
            int cc = wn * 32 + nt * 8 + 2 * tg;
            float b0 = __ldg(ec_b + cc), b1 = __ldg(ec_b + cc + 1);
            *(__half2*)(sm + r * ASTR + cc * 2) =
                __floats2half2_rn(tanha(acc[mt][nt][0] + b0), tanha(acc[mt][nt][1] + b1));
            *(__half2*)(sm + (r + 8) * ASTR + cc * 2) =
                __floats2half2_rn(tanha(acc[mt][nt][2] + b0), tanha(acc[mt][nt][3] + b1));
        }
    }
    __syncthreads();
    for (int it = tid; it < 128 * 16; it += 512) {
        int r = it >> 4, bb = it & 15;
        uint4 v = *(uint4*)(sm + r * ASTR + bb * 16);
        *(uint4*)((char*)g_AE + (size_t)(row0 + r) * 256 + bb * 16) = v;
    }
}

// ---------------- L2: HMMA gate GEMM, j-chunked, complete records per chunk, 2 CTA/SM -----
#define SMJ_A 0
#define SMJ_B (128 * ASTR)                 /* 34816 */
#define SMJ_C (2 * 128 * ASTR)             /* 69632 */
#define SMJ_TOTAL (3 * 128 * ASTR)         /* 104448 */
__global__ __launch_bounds__(512, 2) void k_gemm_mma() {
    extern __shared__ char sm[];
    int tid = threadIdx.x, w = tid >> 5, l = tid & 31;
    int wm = w & 3, wg = w >> 2;           // wg = gate
    int row0 = blockIdx.x * 128;

    const uint4* Ag = (const uint4*)g_AE;
    for (int idx = tid; idx < 128 * 16; idx += 512) {
        int r = idx >> 4, c4 = idx & 15;
        *(uint4*)(sm + SMJ_A + r * ASTR + c4 * 16) = Ag[(size_t)(row0 + r) * 16 + c4];
    }

    uint32_t base = s2u(sm);
    int g8 = l & 7, tg = l & 3, gg = l >> 2;
    uint32_t aBase = base + SMJ_A + (uint32_t)(wm * 32 + g8 + ((l >> 3) & 1) * 8) * ASTR
                   + ((l >> 4) & 1) * 16;
    uint32_t bBase = base + SMJ_B + (uint32_t)(wg * 32 + g8) * ASTR + ((l >> 3) & 1) * 16;
    const uint4* Bg = (const uint4*)g_Bn;

    for (int jc = 0; jc < 4; jc++) {
        // load B chunk (128 reordered rows covering all 4 gates of 32 j's)
        for (int idx = tid; idx < 128 * 16; idx += 512) {
            int n = idx >> 4, c4 = idx & 15;
            *(uint4*)(sm + SMJ_B + n * ASTR + c4 * 16) = Bg[(size_t)(jc * 128 + n) * 16 + c4];
        }
        __syncthreads();   // B ready; also fences prior streamout reads of C

        float acc[2][4][4];
#pragma unroll
        for (int mt = 0; mt < 2; mt++)
#pragma unroll
            for (int nt = 0; nt < 4; nt++)
#pragma unroll
                for (int q = 0; q < 4; q++) acc[mt][nt][q] = 0.0f;

#pragma unroll
        for (int kt = 0; kt < 8; kt++) {
            uint32_t a[2][4];
            ldmA(a[0], aBase + kt * 32);
            ldmA(a[1], aBase + 16 * ASTR + kt * 32);
#pragma unroll
            for (int nt = 0; nt < 4; nt++) {
                uint32_t b[2];
                ldmB(b, bBase + nt * 8 * ASTR + kt * 32);
                mma16816(acc[0][nt], a[0], b);
                mma16816(acc[1][nt], a[1], b);
            }
        }
        __syncthreads();   // all ldmB done before next B load (and before C staging race)

        // stage complete records for this chunk: jp_local = nt*4+tg, slot = wg
#pragma unroll
        for (int mt = 0; mt < 2; mt++) {
            int r = wm * 32 + mt * 16 + gg;
#pragma unroll
            for (int nt = 0; nt < 4; nt++) {
                int off = (nt * 4 + tg) * 16 + wg * 4;
                *(__half2*)(sm + SMJ_C + r * ASTR + off) =
                    __floats2half2_rn(acc[mt][nt][0], acc[mt][nt][1]);
                *(__half2*)(sm + SMJ_C + (r + 8) * ASTR + off) =
                    __floats2half2_rn(acc[mt][nt][2], acc[mt][nt][3]);
            }
        }
        __syncthreads();
        // coalesced streamout: 128 rows x 256B into jp window jc*16..+16
        for (int it = tid; it < 128 * 16; it += 512) {
            int r = it >> 4, q = it & 15;
            uint4 v = *(uint4*)(sm + SMJ_C + r * ASTR + q * 16);
            *(uint4*)((char*)g_G16 + (size_t)(row0 + r) * 1024 + jc * 256 + q * 16) = v;
        }
    }
}

// ---------------- L3: barrier-free HMMA LSTM + mma MLP (10 warps, prefetch) ---------------
#define SL_B  0
#define SL_W1 (512 * ASTR)                        /* 139264 */
#define SL_TOTAL (SL_W1 + 128 * ASTR)             /* 174080 */
__global__ __launch_bounds__(320, 1) void k_lstm_mma(const int* __restrict__ edges,
                                                     const float* __restrict__ mlp_b1,
                                                     const float* __restrict__ mlp_W2,
                                                     const float* __restrict__ mlp_b2,
                                                     float* __restrict__ scores_out) {
    extern __shared__ char sm[];
    int tid = threadIdx.x, w = tid >> 5, l = tid & 31;

    const uint4* Bg = (const uint4*)g_Bh;
    for (int idx = tid; idx < 512 * 16; idx += 320) {
        int n = idx >> 4, c4 = idx & 15;
        *(uint4*)(sm + SL_B + n * ASTR + c4 * 16) = Bg[(size_t)n * 16 + c4];
    }
    const uint4* Wg = (const uint4*)g_W1h;
    for (int idx = tid; idx < 128 * 16; idx += 320) {
        int n = idx >> 4, c4 = idx & 15;
        *(uint4*)(sm + SL_W1 + n * ASTR + c4 * 16) = Wg[(size_t)n * 16 + c4];
    }
    __syncthreads();

    uint32_t base = s2u(sm);
    int g8 = l & 7, t4 = l & 3, gg = l >> 2;
    uint32_t bFrag = base + SL_B + (uint32_t)g8 * ASTR
                   + ((l >> 3) & 1) * 16 + ((l >> 4) & 1) * 32;
    uint32_t wFrag = base + SL_W1 + (uint32_t)g8 * ASTR
                   + ((l >> 3) & 1) * 16 + ((l >> 4) & 1) * 32;

    int seqA = blockIdx.x * 160 + w * 16 + gg;
    int seqB = seqA + 8;
    int bA = seqA / Pn, bB = seqB / Pn;

    float cst[64];
#pragma unroll
    for (int q = 0; q < 64; q++) cst[q] = 0.0f;
    uint32_t hf[8][4];
#pragma unroll
    for (int kk = 0; kk < 8; kk++)
#pragma unroll
        for (int q = 0; q < 4; q++) hf[kk][q] = 0u;

    for (int t = 0; t < Tn; t++) {
        int rowGA = (t == 0) ? NPL + bA : (t == 4) ? NPL + Bsz + bA : seqA * Ln + (t - 1);
        int rowGB = (t == 0) ? NPL + bB : (t == 4) ? NPL + Bsz + bB : seqB * Ln + (t - 1);
        int eA = (t < Ln) ? edges[seqA * Ln + t] : 0;
        int eB = (t < Ln) ? edges[seqB * Ln + t] : 0;
        const char* gAr = (const char*)g_G16 + (size_t)rowGA * 1024 + t4 * 16;
        const char* gBr = (const char*)g_G16 + (size_t)rowGB * 1024 + t4 * 16;
        const char* rAr = (const char*)g_relGb16 + (size_t)eA * 1024 + t4 * 16;
        const char* rBr = (const char*)g_relGb16 + (size_t)eB * 1024 + t4 * 16;

        // prefetch nt=0 records
        uint4 pgA = *(const uint4*)(gAr);
        uint4 pgB = *(const uint4*)(gBr);
        uint4 prA = *(const uint4*)(rAr);
        uint4 prB = *(const uint4*)(rBr);

        uint32_t hn[8][4];
#pragma unroll
        for (int kt = 0; kt < 8; kt++) {
#pragma unroll
            for (int half = 0; half < 2; half++) {
                int nt = kt * 2 + half;
                uint4 guA = pgA, guB = pgB, ruA = prA, ruB = prB;
                if (nt < 15) {       // prefetch next nt (hidden under the mma chain)
                    pgA = *(const uint4*)(gAr + (nt + 1) * 64);
                    pgB = *(const uint4*)(gBr + (nt + 1) * 64);
                    prA = *(const uint4*)(rAr + (nt + 1) * 64);
                    prB = *(const uint4*)(rBr + (nt + 1) * 64);
                }

                float acc[4][4];
#pragma unroll
                for (int g = 0; g < 4; g++)
#pragma unroll
                    for (int q = 0; q < 4; q++) acc[g][q] = 0.0f;
                if (t > 0) {
                    uint32_t tRow = (uint32_t)(nt * 8) * ASTR;
#pragma unroll
                    for (int kp = 0; kp < 4; kp++) {
#pragma unroll
                        for (int g = 0; g < 4; g++) {
                            uint32_t b4[4];
                            ldmB4(b4, bFrag + tRow + (uint32_t)(g * 128) * ASTR + kp * 64);
                            mma16816(acc[g], hf[2 * kp], b4);
                            mma16816(acc[g], hf[2 * kp + 1], b4 + 2);
                        }
                    }
                }
                float2 iA = __half22float2(*(const __half2*)&guA.x);
                float2 fA = __half22float2(*(const __half2*)&guA.y);
                float2 gA = __half22float2(*(const __half2*)&guA.z);
                float2 oA = __half22float2(*(const __half2*)&guA.w);
                float2 iB = __half22float2(*(const __half2*)&guB.x);
                float2 fB = __half22float2(*(const __half2*)&guB.y);
                float2 gB = __half22float2(*(const __half2*)&guB.z);
                float2 oB = __half22float2(*(const __half2*)&guB.w);
                float2 riA = __half22float2(*(const __half2*)&ruA.x);
                float2 rfA = __half22float2(*(const __half2*)&ruA.y);
                float2 rgA = __half22float2(*(const __half2*)&ruA.z);
                float2 roA = __half22float2(*(const __half2*)&ruA.w);
                float2 riB = __half22float2(*(const __half2*)&ruB.x);
                float2 rfB = __half22float2(*(const __half2*)&ruB.y);
                float2 rgB = __half22float2(*(const __half2*)&ruB.z);
                float2 roB = __half22float2(*(const __half2*)&ruB.w);

                int ci = nt * 4;
                float gi = acc[0][0] + iA.x + riA.x;
                float gf = acc[1][0] + fA.x + rfA.x;
                float gG = acc[2][0] + gA.x + rgA.x;
                float gO = acc[3][0] + oA.x + roA.x;
                cst[ci] = siga(gf) * cst[ci] + siga(gi) * tanha(gG);
                float hA0 = siga(gO) * tanha(cst[ci]);
                gi = acc[0][1] + iA.y + riA.y;
                gf = acc[1][1] + fA.y + rfA.y;
                gG = acc[2][1] + gA.y + rgA.y;
                gO = acc[3][1] + oA.y + roA.y;
                cst[ci + 1] = siga(gf) * cst[ci + 1] + siga(gi) * tanha(gG);
                float hA1 = siga(gO) * tanha(cst[ci + 1]);
                gi = acc[0][2] + iB.x + riB.x;
                gf = acc[1][2] + fB.x + rfB.x;
                gG = acc[2][2] + gB.x + rgB.x;
                gO = acc[3][2] + oB.x + roB.x;
                cst[ci + 2] = siga(gf) * cst[ci + 2] + siga(gi) * tanha(gG);
                float hB0 = siga(gO) * tanha(cst[ci + 2]);
                gi = acc[0][3] + iB.y + riB.y;
                gf = acc[1][3] + fB.y + rfB.y;
                gG = acc[2][3] + gB.y + rgB.y;
                gO = acc[3][3] + oB.y + roB.y;
                cst[ci + 3] = siga(gf) * cst[ci + 3] + siga(gi) * tanha(gG);
                float hB1 = siga(gO) * tanha(cst[ci + 3]);

                __half2 pA = __floats2half2_rn(hA0, hA1);
                __half2 pB = __floats2half2_rn(hB0, hB1);
                hn[kt][half * 2]     = *(uint32_t*)&pA;
                hn[kt][half * 2 + 1] = *(uint32_t*)&pB;
            }
        }
#pragma unroll
        for (int kk = 0; kk < 8; kk++)
#pragma unroll
            for (int q = 0; q < 4; q++) hf[kk][q] = hn[kk][q];
    }

    // ---- MLP via mma on register h-fragments ----
    float sc0 = 0.0f, sc1 = 0.0f;
#pragma unroll
    for (int ntg = 0; ntg < 16; ntg++) {
        float acc[4];
#pragma unroll
        for (int q = 0; q < 4; q++) acc[q] = 0.0f;
        uint32_t tRow = (uint32_t)(ntg * 8) * ASTR;
#pragma unroll
        for (int kp = 0; kp < 4; kp++) {
            uint32_t b4[4];
            ldmB4(b4, wFrag + tRow + kp * 64);
            mma16816(acc, hf[2 * kp], b4);
            mma16816(acc, hf[2 * kp + 1], b4 + 2);
        }
        int j0 = ntg * 8 + t4 * 2;
        float b10 = __ldg(mlp_b1 + j0), b11 = __ldg(mlp_b1 + j0 + 1);
        float w20 = __ldg(mlp_W2 + j0), w21 = __ldg(mlp_W2 + j0 + 1);
        sc0 += fmaxf(acc[0] + b10, 0.0f) * w20 + fmaxf(acc[1] + b11, 0.0f) * w21;
        sc1 += fmaxf(acc[2] + b10, 0.0f) * w20 + fmaxf(acc[3] + b11, 0.0f) * w21;
    }
    sc0 += __shfl_xor_sync(0xffffffffu, sc0, 1);
    sc0 += __shfl_xor_sync(0xffffffffu, sc0, 2);
    sc1 += __shfl_xor_sync(0xffffffffu, sc1, 1);
    sc1 += __shfl_xor_sync(0xffffffffu, sc1, 2);
    if (t4 == 0) {
        float b2 = __ldg(mlp_b2);
        scores_out[seqA] = sc0 + b2;
        scores_out[seqB] = sc1 + b2;
    }
}

// ---------------- L4: logsumexp + BCE ----------------
__global__ void k_final(const float* __restrict__ label, float* __restrict__ out) {
    __shared__ float red[Bsz];
    int b = threadIdx.x;
    const float* sc = out + 1 + Bsz + b * Pn;
    float mx = -1e30f;
#pragma unroll
    for (int p = 0; p < Pn; p++) mx = fmaxf(mx, sc[p] * 0.5f);
    float s = 0.0f;
#pragma unroll
    for (int p = 0; p < Pn; p++) s += expf(sc[p] * 0.5f - mx);
    float lse = mx + logf(s);
    float pr = 1.0f / (1.0f + expf(-lse));
    out[1 + b] = pr;
    float pc = fminf(fmaxf(pr, 1e-7f), 1.0f - 1e-7f);
    float lb = label[b];
    red[b] = -(lb * logf(pc) + (1.0f - lb) * logf(1.0f - pc));
    __syncthreads();
    for (int st = Bsz / 2; st > 0; st >>= 1) {
        if (b < st) red[b] += red[b + st];
        __syncthreads();
    }
    if (b == 0) out[0] = red[0] / (float)Bsz;
}

// ---------------- launch ----------------
extern "C" void kernel_launch(void* const* d_in, const int* in_sizes, int n_in,
                              void* d_out, int out_size) {
    const int*   item1     = (const int*)d_in[0];
    const int*   item2     = (const int*)d_in[1];
    const int*   paths     = (const int*)d_in[2];
    const int*   edges     = (const int*)d_in[3];
    const float* label     = (const float*)d_in[4];
    const float* doc_table = (const float*)d_in[5];
    const float* ent_table = (const float*)d_in[6];
    const float* rel_table = (const float*)d_in[7];
    const float* nc_W1 = (const float*)d_in[8];
    const float* nc_b1 = (const float*)d_in[9];
    const float* nc_W2 = (const float*)d_in[10];
    const float* nc_b2 = (const float*)d_in[11];
    const float* ec_W  = (const float*)d_in[12];
    const float* ec_b  = (const float*)d_in[13];
    const float* rc_W  = (const float*)d_in[14];
    const float* rc_b  = (const float*)d_in[15];
    const float* W_ih  = (const float*)d_in[16];
    const float* W_hh  = (const float*)d_in[17];
    const float* b_ih  = (const float*)d_in[18];
    const float* b_hh  = (const float*)d_in[19];
    const float* mlp_W1 = (const float*)d_in[20];
    const float* mlp_b1 = (const float*)d_in[21];
    const float* mlp_W2 = (const float*)d_in[22];
    const float* mlp_b2 = (const float*)d_in[23];
    float* out = (float*)d_out;

    cudaFuncSetAttribute(k_compress_rel, cudaFuncAttributeMaxDynamicSharedMemorySize, SMC_TOTAL);
    cudaFuncSetAttribute(k_gemm_mma, cudaFuncAttributeMaxDynamicSharedMemorySize, SMJ_TOTAL);
    cudaFuncSetAttribute(k_lstm_mma, cudaFuncAttributeMaxDynamicSharedMemorySize, SL_TOTAL);

    k_news_transpose<<<768, 128>>>(item1, item2, doc_table, nc_W1, nc_b1, nc_W2, nc_b2,
                                   W_ih, W_hh, ec_W, mlp_W1);
    k_compress_rel<<<NPL / 128 + NREL, 512, SMC_TOTAL>>>(paths, ent_table, ec_b,
                                                         rel_table, rc_W, rc_b, b_ih, b_hh);
    k_gemm_mma<<<MTOT / 128, 512, SMJ_TOTAL>>>();
    k_lstm_mma<<<Nseq / 160, 320, SL_TOTAL>>>(edges, mlp_b1, mlp_W2, mlp_b2, out + 1 + Bsz);
    k_final<<<1, Bsz>>>(label, out);
}

// round 16
// speedup vs baseline: 1.2331x; 1.0066x over previous
#include <cuda_runtime.h>
#include <cuda_fp16.h>
#include <math.h>
#include <stdint.h>

typedef unsigned long long u64;

#define Bsz   1024
#define Pn    20
#define Ln    3
#define Tn    5
#define En    128
#define Nseq  (Bsz*Pn)          /* 20480 */
#define NPL   (Bsz*Pn*Ln)       /* 61440 */
#define NREL  60
#define DDOC  768
#define DENT  100
#define KPAD  112
#define MTOT  (NPL + 2*Bsz)     /* 63488 = 496*128 */

// ---------------- device scratch ----------------
__device__ __half g_AE [(size_t)MTOT * 128];
__device__ __half g_Bn [512 * 128];             // W_ih[:,0:128], rows reordered: (j>>5)*128+gate*32+(j&31)
__device__ __half g_Bh [512 * 128];             // W_hh, PLAIN rows
__device__ __half g_W1h[128 * 128];             // mlp_W1^T f16: [n][k]
__device__ __half g_Wec[128 * KPAD];
__device__ float  g_WTrel[128 * 512];           // f32 [k][c'] plain
__device__ __half g_relGb16[NREL * 512];        // [e][64 jp][i0,i1,f0,f1,g0,g1,o0,o1]
__device__ __half g_G16 [(size_t)MTOT * 512];   // [row][64 jp][8 gate-halves]

// ---- fast transcendentals ----
__device__ __forceinline__ float tanha(float x) {
    float y; asm("tanh.approx.f32 %0, %1;" : "=f"(y) : "f"(x)); return y;
}
__device__ __forceinline__ float siga(float x) {
    return fmaf(tanha(x * 0.5f), 0.5f, 0.5f);
}

// ---- f32x2 helpers ----
__device__ __forceinline__ u64 ffma2(u64 a, u64 b, u64 c) {
    u64 d; asm("fma.rn.f32x2 %0, %1, %2, %3;" : "=l"(d) : "l"(a), "l"(b), "l"(c)); return d;
}
__device__ __forceinline__ u64 dup2(float x) {
    u64 d; unsigned xi = __float_as_uint(x);
    asm("mov.b64 %0, {%1, %1};" : "=l"(d) : "r"(xi)); return d;
}
__device__ __forceinline__ float2 up2(u64 v) {
    unsigned lo, hi; asm("mov.b64 {%0, %1}, %2;" : "=r"(lo), "=r"(hi) : "l"(v));
    return make_float2(__uint_as_float(lo), __uint_as_float(hi));
}

// ---- mma / ldmatrix ----
__device__ __forceinline__ uint32_t s2u(const void* p) {
    uint32_t a;
    asm("{ .reg .u64 t; cvta.to.shared.u64 t, %1; cvt.u32.u64 %0, t; }" : "=r"(a) : "l"(p));
    return a;
}
__device__ __forceinline__ void ldmA(uint32_t* r, uint32_t addr) {
    asm volatile("ldmatrix.sync.aligned.m8n8.x4.shared.b16 {%0,%1,%2,%3}, [%4];"
                 : "=r"(r[0]), "=r"(r[1]), "=r"(r[2]), "=r"(r[3]) : "r"(addr));
}
__device__ __forceinline__ void ldmB(uint32_t* r, uint32_t addr) {
    asm volatile("ldmatrix.sync.aligned.m8n8.x2.shared.b16 {%0,%1}, [%2];"
                 : "=r"(r[0]), "=r"(r[1]) : "r"(addr));
}
__device__ __forceinline__ void ldmB4(uint32_t* r, uint32_t addr) {
    asm volatile("ldmatrix.sync.aligned.m8n8.x4.shared.b16 {%0,%1,%2,%3}, [%4];"
                 : "=r"(r[0]), "=r"(r[1]), "=r"(r[2]), "=r"(r[3]) : "r"(addr));
}
__device__ __forceinline__ void mma16816(float* d, const uint32_t* a, const uint32_t* b) {
    asm volatile("mma.sync.aligned.m16n8k16.row.col.f32.f16.f16.f32 "
        "{%0,%1,%2,%3}, {%4,%5,%6,%7}, {%8,%9}, {%0,%1,%2,%3};"
        : "+f"(d[0]), "+f"(d[1]), "+f"(d[2]), "+f"(d[3])
        : "r"(a[0]), "r"(a[1]), "r"(a[2]), "r"(a[3]), "r"(b[0]), "r"(b[1]));
}

#define ASTR  272
#define CKSTR 240
#define DSTR  10

// ---------------- L0: news (blocks 0..255) + weight pack (blocks 256..767) ---------------
__global__ void k_news_transpose(const int* __restrict__ item1, const int* __restrict__ item2,
                                 const float* __restrict__ doc_table,
                                 const float* __restrict__ W1, const float* __restrict__ b1,
                                 const float* __restrict__ W2, const float* __restrict__ b2,
                                 const float* __restrict__ W_ih, const float* __restrict__ W_hh,
                                 const float* __restrict__ ec_W, const float* __restrict__ mlp_W1) {
    __shared__ __align__(16) float dsp[DDOC * DSTR];
    __shared__ __align__(16) float h1p[En * DSTR];
    __shared__ int items[8];
    int tid = threadIdx.x;

    if (blockIdx.x >= 256) {
        int idx = (blockIdx.x - 256) * 128 + tid;
        if (idx < 128 * KPAD) {
            int c = idx / KPAD, k = idx - c * KPAD;
            g_Wec[idx] = (k < DENT) ? __float2half_rn(ec_W[k * 128 + c]) : __half(0.0f);
        }
        if (idx < 128 * 128) {
            int n = idx >> 7, k = idx & 127;
            g_W1h[idx] = __float2half_rn(mlp_W1[k * 128 + n]);
        }
        int c = idx >> 7, k = idx & 127;   // c = torch row = gate*128 + j
        int gate = c >> 7, j = c & 127;
        int c2 = (j >> 5) * 128 + gate * 32 + (j & 31);   // j-chunk-major reorder
        g_Bn[c2 * 128 + k] = __float2half_rn(W_ih[c * 256 + k]);
        g_Bh[idx] = __float2half_rn(W_hh[c * 128 + k]);
        g_WTrel[k * 512 + c] = W_ih[c * 256 + 128 + k];
        return;
    }

    int r0 = blockIdx.x * 8;
    if (tid < 8) {
        int row = r0 + tid;
        items[tid] = (row < Bsz) ? item1[row] : item2[row - Bsz];
    }
    __syncthreads();
    for (int k = tid; k < DDOC; k += 128) {
#pragma unroll
        for (int r = 0; r < 8; r++)
            dsp[k * DSTR + r] = doc_table[(size_t)items[r] * DDOC + k];
    }
    __syncthreads();
    u64 acc2[4];
    u64 bd = dup2(b1[tid]);
#pragma unroll
    for (int p = 0; p < 4; p++) acc2[p] = bd;
    for (int k = 0; k < DDOC; k++) {
        u64 wd = dup2(W1[k * En + tid]);
        const u64* hp = (const u64*)&dsp[k * DSTR];
#pragma unroll
        for (int p = 0; p < 4; p++) acc2[p] = ffma2(hp[p], wd, acc2[p]);
    }
#pragma unroll
    for (int p = 0; p < 4; p++) {
        float2 a = up2(acc2[p]);
        h1p[tid * DSTR + 2 * p]     = (a.x > 0.0f) ? a.x : expm1f(a.x);
        h1p[tid * DSTR + 2 * p + 1] = (a.y > 0.0f) ? a.y : expm1f(a.y);
    }
    __syncthreads();
    u64 bd2 = dup2(b2[tid]);
#pragma unroll
    for (int p = 0; p < 4; p++) acc2[p] = bd2;
    for (int k = 0; k < En; k++) {
        u64 wd = dup2(W2[k * En + tid]);
        const u64* hp = (const u64*)&h1p[k * DSTR];
#pragma unroll
        for (int p = 0; p < 4; p++) acc2[p] = ffma2(hp[p], wd, acc2[p]);
    }
#pragma unroll
    for (int p = 0; p < 4; p++) {
        float2 a = up2(acc2[p]);
        g_AE[(size_t)(NPL + r0 + 2 * p)     * En + tid] = __float2half_rn(tanhf(a.x));
        g_AE[(size_t)(NPL + r0 + 2 * p + 1) * En + tid] = __float2half_rn(tanhf(a.y));
    }
}

// ---------------- L1: entity compress (blocks 0..479) + relations (480..539) --------------
#define SMC_A 0
#define SMC_B (128 * CKSTR)
#define SMC_TOTAL (2 * 128 * CKSTR)
__global__ __launch_bounds__(512, 2) void k_compress_rel(const int* __restrict__ paths,
                                                         const float* __restrict__ ent_table,
                                                         const float* __restrict__ ec_b,
                                                         const float* __restrict__ rel_table,
                                                         const float* __restrict__ rc_W,
                                                         const float* __restrict__ rc_b,
                                                         const float* __restrict__ b_ih,
                                                         const float* __restrict__ b_hh) {
    extern __shared__ char sm[];
    __shared__ int spath[128];
    __shared__ float rr[DENT];
    __shared__ float rcs[En];
    int tid = threadIdx.x;

    if (blockIdx.x >= NPL / 128) {
        int rrow = blockIdx.x - NPL / 128;
        if (tid < DENT) rr[tid] = rel_table[rrow * DENT + tid];
        __syncthreads();
        if (tid < En) {
            float s = rc_b[tid];
            for (int k = 0; k < DENT; k++) s += rr[k] * rc_W[k * En + tid];
            rcs[tid] = tanhf(s);
        }
        __syncthreads();
        int c = tid;
        int gate = c >> 7, j = c & 127;
        float s = b_ih[c] + b_hh[c];
        for (int k = 0; k < En; k++) s += rcs[k] * g_WTrel[k * 512 + c];
        g_relGb16[rrow * 512 + (j >> 1) * 8 + gate * 2 + (j & 1)] = __float2half_rn(s);
        return;
    }

    int w = tid >> 5, l = tid & 31;
    int wm = w & 3, wn = w >> 2;
    int row0 = blockIdx.x * 128;

    if (tid < 128) spath[tid] = paths[row0 + tid];
    __syncthreads();
    for (int idx = tid; idx < 128 * 25; idx += 512) {
        int r = idx / 25, k4 = idx - r * 25;
        float4 v = *(const float4*)(ent_table + (size_t)spath[r] * DENT + k4 * 4);
        uint2 u2;
        *((__half2*)&u2.x) = __floats2half2_rn(v.x, v.y);
        *((__half2*)&u2.y) = __floats2half2_rn(v.z, v.w);
        *(uint2*)(sm + SMC_A + r * CKSTR + k4 * 8) = u2;
    }
    for (int idx = tid; idx < 128 * 3; idx += 512) {
        int r = idx / 3, j = idx - r * 3;
        *(uint2*)(sm + SMC_A + r * CKSTR + 200 + j * 8) = make_uint2(0u, 0u);
    }
    for (int idx = tid; idx < 128 * 28; idx += 512) {
        int r = idx / 28, j = idx - r * 28;
        *(uint2*)(sm + SMC_B + r * CKSTR + j * 8) = ((const uint2*)g_Wec)[idx];
    }
    __syncthreads();

    uint32_t base = s2u(sm);
    int g8 = l & 7;
    uint32_t aBase = base + SMC_A + (uint32_t)(wm * 32 + g8 + ((l >> 3) & 1) * 8) * CKSTR
                   + ((l >> 4) & 1) * 16;
    uint32_t bBase = base + SMC_B + (uint32_t)(wn * 32 + g8) * CKSTR + ((l >> 3) & 1) * 16;

    float acc[2][4][4];
#pragma unroll
    for (int mt = 0; mt < 2; mt++)
#pragma unroll
        for (int nt = 0; nt < 4; nt++)
#pragma unroll
            for (int q = 0; q < 4; q++) acc[mt][nt][q] = 0.0f;

#pragma unroll
    for (int kt = 0; kt < 7; kt++) {
        uint32_t a[2][4];
        ldmA(a[0], aBase + kt * 32);
        ldmA(a[1], aBase + 16 * CKSTR + kt * 32);
#pragma unroll
        for (int nt = 0; nt < 4; nt++) {
            uint32_t b[2];
            ldmB(b, bBase + nt * 8 * CKSTR + kt * 32);
            mma16816(acc[0][nt], a[0], b);
            mma16816(acc[1][nt], a[1], b);
        }
    }
    __syncthreads();

    int tg = l & 3, gg = l >> 2;
#pragma unroll
    for (int mt = 0; mt < 2; mt++) {
        int r = wm * 32 + mt * 16 + gg;
#pragma unroll
        for (int nt = 0; nt < 4; nt++) {
            int cc = wn * 32 + nt * 8 + 2 * tg;
            float b0 = __ldg(ec_b + cc), b1 = __ldg(ec_b + cc + 1);
            *(__half2*)(sm + r * ASTR + cc * 2) =
                __floats2half2_rn(tanha(acc[mt][nt][0] + b0), tanha(acc[mt][nt][1] + b1));
            *(__half2*)(sm + (r + 8) * ASTR + cc * 2) =
                __floats2half2_rn(tanha(acc[mt][nt][2] + b0), tanha(acc[mt][nt][3] + b1));
        }
    }
    __syncthreads();
    for (int it = tid; it < 128 * 16; it += 512) {
        int r = it >> 4, bb = it & 15;
        uint4 v = *(uint4*)(sm + r * ASTR + bb * 16);
        *(uint4*)((char*)g_AE + (size_t)(row0 + r) * 256 + bb * 16) = v;
    }
}

// ---------------- L2: HMMA gate GEMM, j-chunked, complete records per chunk, 2 CTA/SM -----
#define SMJ_A 0
#define SMJ_B (128 * ASTR)                 /* 34816 */
#define SMJ_C (2 * 128 * ASTR)             /* 69632 */
#define SMJ_TOTAL (3 * 128 * ASTR)         /* 104448 */
__global__ __launch_bounds__(512, 2) void k_gemm_mma() {
    extern __shared__ char sm[];
    int tid = threadIdx.x, w = tid >> 5, l = tid & 31;
    int wm = w & 3, wg = w >> 2;           // wg = gate
    int row0 = blockIdx.x * 128;

    const uint4* Ag = (const uint4*)g_AE;
    for (int idx = tid; idx < 128 * 16; idx += 512) {
        int r = idx >> 4, c4 = idx & 15;
        *(uint4*)(sm + SMJ_A + r * ASTR + c4 * 16) = Ag[(size_t)(row0 + r) * 16 + c4];
    }

    uint32_t base = s2u(sm);
    int g8 = l & 7, tg = l & 3, gg = l >> 2;
    uint32_t aBase = base + SMJ_A + (uint32_t)(wm * 32 + g8 + ((l >> 3) & 1) * 8) * ASTR
                   + ((l >> 4) & 1) * 16;
    uint32_t bBase = base + SMJ_B + (uint32_t)(wg * 32 + g8) * ASTR + ((l >> 3) & 1) * 16;
    const uint4* Bg = (const uint4*)g_Bn;

    for (int jc = 0; jc < 4; jc++) {
        for (int idx = tid; idx < 128 * 16; idx += 512) {
            int n = idx >> 4, c4 = idx & 15;
            *(uint4*)(sm + SMJ_B + n * ASTR + c4 * 16) = Bg[(size_t)(jc * 128 + n) * 16 + c4];
        }
        __syncthreads();

        float acc[2][4][4];
#pragma unroll
        for (int mt = 0; mt < 2; mt++)
#pragma unroll
            for (int nt = 0; nt < 4; nt++)
#pragma unroll
                for (int q = 0; q < 4; q++) acc[mt][nt][q] = 0.0f;

#pragma unroll
        for (int kt = 0; kt < 8; kt++) {
            uint32_t a[2][4];
            ldmA(a[0], aBase + kt * 32);
            ldmA(a[1], aBase + 16 * ASTR + kt * 32);
#pragma unroll
            for (int nt = 0; nt < 4; nt++) {
                uint32_t b[2];
                ldmB(b, bBase + nt * 8 * ASTR + kt * 32);
                mma16816(acc[0][nt], a[0], b);
                mma16816(acc[1][nt], a[1], b);
            }
        }
        __syncthreads();

#pragma unroll
        for (int mt = 0; mt < 2; mt++) {
            int r = wm * 32 + mt * 16 + gg;
#pragma unroll
            for (int nt = 0; nt < 4; nt++) {
                int off = (nt * 4 + tg) * 16 + wg * 4;
                *(__half2*)(sm + SMJ_C + r * ASTR + off) =
                    __floats2half2_rn(acc[mt][nt][0], acc[mt][nt][1]);
                *(__half2*)(sm + SMJ_C + (r + 8) * ASTR + off) =
                    __floats2half2_rn(acc[mt][nt][2], acc[mt][nt][3]);
            }
        }
        __syncthreads();
        for (int it = tid; it < 128 * 16; it += 512) {
            int r = it >> 4, q = it & 15;
            uint4 v = *(uint4*)(sm + SMJ_C + r * ASTR + q * 16);
            *(uint4*)((char*)g_G16 + (size_t)(row0 + r) * 1024 + jc * 256 + q * 16) = v;
        }
    }
}

// ---------------- L3: barrier-free HMMA LSTM + mma MLP (12 warps, single wave) ------------
#define SL_B  0
#define SL_W1 (512 * ASTR)                        /* 139264 */
#define SL_TOTAL (SL_W1 + 128 * ASTR)             /* 174080 */
__global__ __launch_bounds__(384, 1) void k_lstm_mma(const int* __restrict__ edges,
                                                     const float* __restrict__ mlp_b1,
                                                     const float* __restrict__ mlp_W2,
                                                     const float* __restrict__ mlp_b2,
                                                     float* __restrict__ scores_out) {
    extern __shared__ char sm[];
    int tid = threadIdx.x, w = tid >> 5, l = tid & 31;

    const uint4* Bg = (const uint4*)g_Bh;
    for (int idx = tid; idx < 512 * 16; idx += 384) {
        int n = idx >> 4, c4 = idx & 15;
        *(uint4*)(sm + SL_B + n * ASTR + c4 * 16) = Bg[(size_t)n * 16 + c4];
    }
    const uint4* Wg = (const uint4*)g_W1h;
    for (int idx = tid; idx < 128 * 16; idx += 384) {
        int n = idx >> 4, c4 = idx & 15;
        *(uint4*)(sm + SL_W1 + n * ASTR + c4 * 16) = Wg[(size_t)n * 16 + c4];
    }
    __syncthreads();

    int g8 = l & 7, t4 = l & 3, gg = l >> 2;
    int seqA = blockIdx.x * 192 + w * 16 + gg;
    if (seqA >= Nseq) return;                      // tail warps (no barriers follow)
    int seqB = seqA + 8;
    int bA = seqA / Pn, bB = seqB / Pn;

    uint32_t base = s2u(sm);
    uint32_t bFrag = base + SL_B + (uint32_t)g8 * ASTR
                   + ((l >> 3) & 1) * 16 + ((l >> 4) & 1) * 32;
    uint32_t wFrag = base + SL_W1 + (uint32_t)g8 * ASTR
                   + ((l >> 3) & 1) * 16 + ((l >> 4) & 1) * 32;

    float cst[64];
#pragma unroll
    for (int q = 0; q < 64; q++) cst[q] = 0.0f;
    uint32_t hf[8][4];
#pragma unroll
    for (int kk = 0; kk < 8; kk++)
#pragma unroll
        for (int q = 0; q < 4; q++) hf[kk][q] = 0u;

    for (int t = 0; t < Tn; t++) {
        int rowGA = (t == 0) ? NPL + bA : (t == 4) ? NPL + Bsz + bA : seqA * Ln + (t - 1);
        int rowGB = (t == 0) ? NPL + bB : (t == 4) ? NPL + Bsz + bB : seqB * Ln + (t - 1);
        int eA = (t < Ln) ? edges[seqA * Ln + t] : 0;
        int eB = (t < Ln) ? edges[seqB * Ln + t] : 0;
        const char* gAr = (const char*)g_G16 + (size_t)rowGA * 1024 + t4 * 16;
        const char* gBr = (const char*)g_G16 + (size_t)rowGB * 1024 + t4 * 16;
        const char* rAr = (const char*)g_relGb16 + (size_t)eA * 1024 + t4 * 16;
        const char* rBr = (const char*)g_relGb16 + (size_t)eB * 1024 + t4 * 16;

        uint32_t hn[8][4];
#pragma unroll
        for (int kt = 0; kt < 8; kt++) {
#pragma unroll
            for (int half = 0; half < 2; half++) {
                int nt = kt * 2 + half;
                uint4 guA = *(const uint4*)(gAr + nt * 64);
                uint4 guB = *(const uint4*)(gBr + nt * 64);
                uint4 ruA = *(const uint4*)(rAr + nt * 64);
                uint4 ruB = *(const uint4*)(rBr + nt * 64);

                float acc[4][4];
#pragma unroll
                for (int g = 0; g < 4; g++)
#pragma unroll
                    for (int q = 0; q < 4; q++) acc[g][q] = 0.0f;
                if (t > 0) {
                    uint32_t tRow = (uint32_t)(nt * 8) * ASTR;
#pragma unroll
                    for (int kp = 0; kp < 4; kp++) {
#pragma unroll
                        for (int g = 0; g < 4; g++) {
                            uint32_t b4[4];
                            ldmB4(b4, bFrag + tRow + (uint32_t)(g * 128) * ASTR + kp * 64);
                            mma16816(acc[g], hf[2 * kp], b4);
                            mma16816(acc[g], hf[2 * kp + 1], b4 + 2);
                        }
                    }
                }
                float2 iA = __half22float2(*(const __half2*)&guA.x);
                float2 fA = __half22float2(*(const __half2*)&guA.y);
                float2 gA = __half22float2(*(const __half2*)&guA.z);
                float2 oA = __half22float2(*(const __half2*)&guA.w);
                float2 iB = __half22float2(*(const __half2*)&guB.x);
                float2 fB = __half22float2(*(const __half2*)&guB.y);
                float2 gB = __half22float2(*(const __half2*)&guB.z);
                float2 oB = __half22float2(*(const __half2*)&guB.w);
                float2 riA = __half22float2(*(const __half2*)&ruA.x);
                float2 rfA = __half22float2(*(const __half2*)&ruA.y);
                float2 rgA = __half22float2(*(const __half2*)&ruA.z);
                float2 roA = __half22float2(*(const __half2*)&ruA.w);
                float2 riB = __half22float2(*(const __half2*)&ruB.x);
                float2 rfB = __half22float2(*(const __half2*)&ruB.y);
                float2 rgB = __half22float2(*(const __half2*)&ruB.z);
                float2 roB = __half22float2(*(const __half2*)&ruB.w);

                int ci = nt * 4;
                float gi = acc[0][0] + iA.x + riA.x;
                float gf = acc[1][0] + fA.x + rfA.x;
                float gG = acc[2][0] + gA.x + rgA.x;
                float gO = acc[3][0] + oA.x + roA.x;
                cst[ci] = siga(gf) * cst[ci] + siga(gi) * tanha(gG);
                float hA0 = siga(gO) * tanha(cst[ci]);
                gi = acc[0][1] + iA.y + riA.y;
                gf = acc[1][1] + fA.y + rfA.y;
                gG = acc[2][1] + gA.y + rgA.y;
                gO = acc[3][1] + oA.y + roA.y;
                cst[ci + 1] = siga(gf) * cst[ci + 1] + siga(gi) * tanha(gG);
                float hA1 = siga(gO) * tanha(cst[ci + 1]);
                gi = acc[0][2] + iB.x + riB.x;
                gf = acc[1][2] + fB.x + rfB.x;
                gG = acc[2][2] + gB.x + rgB.x;
                gO = acc[3][2] + oB.x + roB.x;
                cst[ci + 2] = siga(gf) * cst[ci + 2] + siga(gi) * tanha(gG);
                float hB0 = siga(gO) * tanha(cst[ci + 2]);
                gi = acc[0][3] + iB.y + riB.y;
                gf = acc[1][3] + fB.y + rfB.y;
                gG = acc[2][3] + gB.y + rgB.y;
                gO = acc[3][3] + oB.y + roB.y;
                cst[ci + 3] = siga(gf) * cst[ci + 3] + siga(gi) * tanha(gG);
                float hB1 = siga(gO) * tanha(cst[ci + 3]);

                __half2 pA = __floats2half2_rn(hA0, hA1);
                __half2 pB = __floats2half2_rn(hB0, hB1);
                hn[kt][half * 2]     = *(uint32_t*)&pA;
                hn[kt][half * 2 + 1] = *(uint32_t*)&pB;
            }
        }
#pragma unroll
        for (int kk = 0; kk < 8; kk++)
#pragma unroll
            for (int q = 0; q < 4; q++) hf[kk][q] = hn[kk][q];
    }

    // ---- MLP via mma on register h-fragments ----
    float sc0 = 0.0f, sc1 = 0.0f;
#pragma unroll
    for (int ntg = 0; ntg < 16; ntg++) {
        float acc[4];
#pragma unroll
        for (int q = 0; q < 4; q++) acc[q] = 0.0f;
        uint32_t tRow = (uint32_t)(ntg * 8) * ASTR;
#pragma unroll
        for (int kp = 0; kp < 4; kp++) {
            uint32_t b4[4];
            ldmB4(b4, wFrag + tRow + kp * 64);
            mma16816(acc, hf[2 * kp], b4);
            mma16816(acc, hf[2 * kp + 1], b4 + 2);
        }
        int j0 = ntg * 8 + t4 * 2;
        float b10 = __ldg(mlp_b1 + j0), b11 = __ldg(mlp_b1 + j0 + 1);
        float w20 = __ldg(mlp_W2 + j0), w21 = __ldg(mlp_W2 + j0 + 1);
        sc0 += fmaxf(acc[0] + b10, 0.0f) * w20 + fmaxf(acc[1] + b11, 0.0f) * w21;
        sc1 += fmaxf(acc[2] + b10, 0.0f) * w20 + fmaxf(acc[3] + b11, 0.0f) * w21;
    }
    sc0 += __shfl_xor_sync(0xffffffffu, sc0, 1);
    sc0 += __shfl_xor_sync(0xffffffffu, sc0, 2);
    sc1 += __shfl_xor_sync(0xffffffffu, sc1, 1);
    sc1 += __shfl_xor_sync(0xffffffffu, sc1, 2);
    if (t4 == 0) {
        float b2 = __ldg(mlp_b2);
        scores_out[seqA] = sc0 + b2;
        scores_out[seqB] = sc1 + b2;
    }
}

// ---------------- L4: logsumexp + BCE ----------------
__global__ void k_final(const float* __restrict__ label, float* __restrict__ out) {
    __shared__ float red[Bsz];
    int b = threadIdx.x;
    const float* sc = out + 1 + Bsz + b * Pn;
    float mx = -1e30f;
#pragma unroll
    for (int p = 0; p < Pn; p++) mx = fmaxf(mx, sc[p] * 0.5f);
    float s = 0.0f;
#pragma unroll
    for (int p = 0; p < Pn; p++) s += expf(sc[p] * 0.5f - mx);
    float lse = mx + logf(s);
    float pr = 1.0f / (1.0f + expf(-lse));
    out[1 + b] = pr;
    float pc = fminf(fmaxf(pr, 1e-7f), 1.0f - 1e-7f);
    float lb = label[b];
    red[b] = -(lb * logf(pc) + (1.0f - lb) * logf(1.0f - pc));
    __syncthreads();
    for (int st = Bsz / 2; st > 0; st >>= 1) {
        if (b < st) red[b] += red[b + st];
        __syncthreads();
    }
    if (b == 0) out[0] = red[0] / (float)Bsz;
}

// ---------------- launch ----------------
extern "C" void kernel_launch(void* const* d_in, const int* in_sizes, int n_in,
                              void* d_out, int out_size) {
    const int*   item1     = (const int*)d_in[0];
    const int*   item2     = (const int*)d_in[1];
    const int*   paths     = (const int*)d_in[2];
    const int*   edges     = (const int*)d_in[3];
    const float* label     = (const float*)d_in[4];
    const float* doc_table = (const float*)d_in[5];
    const float* ent_table = (const float*)d_in[6];
    const float* rel_table = (const float*)d_in[7];
    const float* nc_W1 = (const float*)d_in[8];
    const float* nc_b1 = (const float*)d_in[9];
    const float* nc_W2 = (const float*)d_in[10];
    const float* nc_b2 = (const float*)d_in[11];
    const float* ec_W  = (const float*)d_in[12];
    const float* ec_b  = (const float*)d_in[13];
    const float* rc_W  = (const float*)d_in[14];
    const float* rc_b  = (const float*)d_in[15];
    const float* W_ih  = (const float*)d_in[16];
    const float* W_hh  = (const float*)d_in[17];
    const float* b_ih  = (const float*)d_in[18];
    const float* b_hh  = (const float*)d_in[19];
    const float* mlp_W1 = (const float*)d_in[20];
    const float* mlp_b1 = (const float*)d_in[21];
    const float* mlp_W2 = (const float*)d_in[22];
    const float* mlp_b2 = (const float*)d_in[23];
    float* out = (float*)d_out;

    cudaFuncSetAttribute(k_compress_rel, cudaFuncAttributeMaxDynamicSharedMemorySize, SMC_TOTAL);
    cudaFuncSetAttribute(k_gemm_mma, cudaFuncAttributeMaxDynamicSharedMemorySize, SMJ_TOTAL);
    cudaFuncSetAttribute(k_lstm_mma, cudaFuncAttributeMaxDynamicSharedMemorySize, SL_TOTAL);

    k_news_transpose<<<768, 128>>>(item1, item2, doc_table, nc_W1, nc_b1, nc_W2, nc_b2,
                                   W_ih, W_hh, ec_W, mlp_W1);
    k_compress_rel<<<NPL / 128 + NREL, 512, SMC_TOTAL>>>(paths, ent_table, ec_b,
                                                         rel_table, rc_W, rc_b, b_ih, b_hh);
    k_gemm_mma<<<MTOT / 128, 512, SMJ_TOTAL>>>();
    k_lstm_mma<<<(Nseq + 191) / 192, 384, SL_TOTAL>>>(edges, mlp_b1, mlp_W2, mlp_b2,
                                                      out + 1 + Bsz);
    k_final<<<1, Bsz>>>(label, out);
}

// round 17
// speedup vs baseline: 1.3125x; 1.0644x over previous
#include <cuda_runtime.h>
#include <cuda_fp16.h>
#include <math.h>
#include <stdint.h>

typedef unsigned long long u64;

#define Bsz   1024
#define Pn    20
#define Ln    3
#define Tn    5
#define En    128
#define Nseq  (Bsz*Pn)          /* 20480 */
#define NPL   (Bsz*Pn*Ln)       /* 61440 */
#define NREL  60
#define DDOC  768
#define DENT  100
#define KPAD  112
#define MTOT  (NPL + 2*Bsz)     /* 63488 = 496*128 */

// ---------------- device scratch ----------------
__device__ __half g_AE [(size_t)MTOT * 128];
__device__ __half g_Bn [512 * 128];             // W_ih[:,0:128], rows reordered: (j>>5)*128+gate*32+(j&31)
__device__ __half g_Bh [512 * 128];             // W_hh, PLAIN rows
__device__ __half g_W1h[128 * 128];             // mlp_W1^T f16: [n][k]
__device__ __half g_Wec[128 * KPAD];
__device__ float  g_WTrel[128 * 512];           // f32 [k][c'] plain
__device__ __half g_relGb16[NREL * 512];        // [e][64 jp][i0,i1,f0,f1,g0,g1,o0,o1]
__device__ __half g_G16 [(size_t)MTOT * 512];   // [row][64 jp][8 gate-halves]

// ---- fast transcendentals ----
__device__ __forceinline__ float tanha(float x) {
    float y; asm("tanh.approx.f32 %0, %1;" : "=f"(y) : "f"(x)); return y;
}
__device__ __forceinline__ uint32_t tanh2u(uint32_t x) {
    uint32_t y; asm("tanh.approx.f16x2 %0, %1;" : "=r"(y) : "r"(x)); return y;
}
__device__ __forceinline__ __half2 tanh2(__half2 x) {
    uint32_t r = tanh2u(*(uint32_t*)&x); return *(__half2*)&r;
}
__device__ __forceinline__ __half2 sig2(__half2 x) {
    const __half2 h = __float2half2_rn(0.5f);
    return __hfma2(tanh2(__hmul2(x, h)), h, h);
}

// ---- f32x2 helpers ----
__device__ __forceinline__ u64 ffma2(u64 a, u64 b, u64 c) {
    u64 d; asm("fma.rn.f32x2 %0, %1, %2, %3;" : "=l"(d) : "l"(a), "l"(b), "l"(c)); return d;
}
__device__ __forceinline__ u64 dup2(float x) {
    u64 d; unsigned xi = __float_as_uint(x);
    asm("mov.b64 %0, {%1, %1};" : "=l"(d) : "r"(xi)); return d;
}
__device__ __forceinline__ float2 up2(u64 v) {
    unsigned lo, hi; asm("mov.b64 {%0, %1}, %2;" : "=r"(lo), "=r"(hi) : "l"(v));
    return make_float2(__uint_as_float(lo), __uint_as_float(hi));
}

// ---- mma / ldmatrix ----
__device__ __forceinline__ uint32_t s2u(const void* p) {
    uint32_t a;
    asm("{ .reg .u64 t; cvta.to.shared.u64 t, %1; cvt.u32.u64 %0, t; }" : "=r"(a) : "l"(p));
    return a;
}
__device__ __forceinline__ void ldmA(uint32_t* r, uint32_t addr) {
    asm volatile("ldmatrix.sync.aligned.m8n8.x4.shared.b16 {%0,%1,%2,%3}, [%4];"
                 : "=r"(r[0]), "=r"(r[1]), "=r"(r[2]), "=r"(r[3]) : "r"(addr));
}
__device__ __forceinline__ void ldmB(uint32_t* r, uint32_t addr) {
    asm volatile("ldmatrix.sync.aligned.m8n8.x2.shared.b16 {%0,%1}, [%2];"
                 : "=r"(r[0]), "=r"(r[1]) : "r"(addr));
}
__device__ __forceinline__ void ldmB4(uint32_t* r, uint32_t addr) {
    asm volatile("ldmatrix.sync.aligned.m8n8.x4.shared.b16 {%0,%1,%2,%3}, [%4];"
                 : "=r"(r[0]), "=r"(r[1]), "=r"(r[2]), "=r"(r[3]) : "r"(addr));
}
__device__ __forceinline__ void mma16816(float* d, const uint32_t* a, const uint32_t* b) {
    asm volatile("mma.sync.aligned.m16n8k16.row.col.f32.f16.f16.f32 "
        "{%0,%1,%2,%3}, {%4,%5,%6,%7}, {%8,%9}, {%0,%1,%2,%3};"
        : "+f"(d[0]), "+f"(d[1]), "+f"(d[2]), "+f"(d[3])
        : "r"(a[0]), "r"(a[1]), "r"(a[2]), "r"(a[3]), "r"(b[0]), "r"(b[1]));
}

#define ASTR  272
#define CKSTR 240
#define DSTR  10

// ---------------- L0: news (blocks 0..255) + weight pack (blocks 256..767) ---------------
__global__ void k_news_transpose(const int* __restrict__ item1, const int* __restrict__ item2,
                                 const float* __restrict__ doc_table,
                                 const float* __restrict__ W1, const float* __restrict__ b1,
                                 const float* __restrict__ W2, const float* __restrict__ b2,
                                 const float* __restrict__ W_ih, const float* __restrict__ W_hh,
                                 const float* __restrict__ ec_W, const float* __restrict__ mlp_W1) {
    __shared__ __align__(16) float dsp[DDOC * DSTR];
    __shared__ __align__(16) float h1p[En * DSTR];
    __shared__ int items[8];
    int tid = threadIdx.x;

    if (blockIdx.x >= 256) {
        int idx = (blockIdx.x - 256) * 128 + tid;
        if (idx < 128 * KPAD) {
            int c = idx / KPAD, k = idx - c * KPAD;
            g_Wec[idx] = (k < DENT) ? __float2half_rn(ec_W[k * 128 + c]) : __half(0.0f);
        }
        if (idx < 128 * 128) {
            int n = idx >> 7, k = idx & 127;
            g_W1h[idx] = __float2half_rn(mlp_W1[k * 128 + n]);
        }
        int c = idx >> 7, k = idx & 127;   // c = torch row = gate*128 + j
        int gate = c >> 7, j = c & 127;
        int c2 = (j >> 5) * 128 + gate * 32 + (j & 31);
        g_Bn[c2 * 128 + k] = __float2half_rn(W_ih[c * 256 + k]);
        g_Bh[idx] = __float2half_rn(W_hh[c * 128 + k]);
        g_WTrel[k * 512 + c] = W_ih[c * 256 + 128 + k];
        return;
    }

    int r0 = blockIdx.x * 8;
    if (tid < 8) {
        int row = r0 + tid;
        items[tid] = (row < Bsz) ? item1[row] : item2[row - Bsz];
    }
    __syncthreads();
    for (int k = tid; k < DDOC; k += 128) {
#pragma unroll
        for (int r = 0; r < 8; r++)
            dsp[k * DSTR + r] = doc_table[(size_t)items[r] * DDOC + k];
    }
    __syncthreads();
    u64 acc2[4];
    u64 bd = dup2(b1[tid]);
#pragma unroll
    for (int p = 0; p < 4; p++) acc2[p] = bd;
    for (int k = 0; k < DDOC; k++) {
        u64 wd = dup2(W1[k * En + tid]);
        const u64* hp = (const u64*)&dsp[k * DSTR];
#pragma unroll
        for (int p = 0; p < 4; p++) acc2[p] = ffma2(hp[p], wd, acc2[p]);
    }
#pragma unroll
    for (int p = 0; p < 4; p++) {
        float2 a = up2(acc2[p]);
        h1p[tid * DSTR + 2 * p]     = (a.x > 0.0f) ? a.x : expm1f(a.x);
        h1p[tid * DSTR + 2 * p + 1] = (a.y > 0.0f) ? a.y : expm1f(a.y);
    }
    __syncthreads();
    u64 bd2 = dup2(b2[tid]);
#pragma unroll
    for (int p = 0; p < 4; p++) acc2[p] = bd2;
    for (int k = 0; k < En; k++) {
        u64 wd = dup2(W2[k * En + tid]);
        const u64* hp = (const u64*)&h1p[k * DSTR];
#pragma unroll
        for (int p = 0; p < 4; p++) acc2[p] = ffma2(hp[p], wd, acc2[p]);
    }
#pragma unroll
    for (int p = 0; p < 4; p++) {
        float2 a = up2(acc2[p]);
        g_AE[(size_t)(NPL + r0 + 2 * p)     * En + tid] = __float2half_rn(tanhf(a.x));
        g_AE[(size_t)(NPL + r0 + 2 * p + 1) * En + tid] = __float2half_rn(tanhf(a.y));
    }
}

// ---------------- L1: entity compress (blocks 0..479) + relations (480..539) --------------
#define SMC_A 0
#define SMC_B (128 * CKSTR)
#define SMC_TOTAL (2 * 128 * CKSTR)
__global__ __launch_bounds__(512, 2) void k_compress_rel(const int* __restrict__ paths,
                                                         const float* __restrict__ ent_table,
                                                         const float* __restrict__ ec_b,
                                                         const float* __restrict__ rel_table,
                                                         const float* __restrict__ rc_W,
                                                         const float* __restrict__ rc_b,
                                                         const float* __restrict__ b_ih,
                                                         const float* __restrict__ b_hh) {
    extern __shared__ char sm[];
    __shared__ int spath[128];
    __shared__ float rr[DENT];
    __shared__ float rcs[En];
    int tid = threadIdx.x;

    if (blockIdx.x >= NPL / 128) {
        int rrow = blockIdx.x - NPL / 128;
        if (tid < DENT) rr[tid] = rel_table[rrow * DENT + tid];
        __syncthreads();
        if (tid < En) {
            float s = rc_b[tid];
            for (int k = 0; k < DENT; k++) s += rr[k] * rc_W[k * En + tid];
            rcs[tid] = tanhf(s);
        }
        __syncthreads();
        int c = tid;
        int gate = c >> 7, j = c & 127;
        float s = b_ih[c] + b_hh[c];
        for (int k = 0; k < En; k++) s += rcs[k] * g_WTrel[k * 512 + c];
        g_relGb16[rrow * 512 + (j >> 1) * 8 + gate * 2 + (j & 1)] = __float2half_rn(s);
        return;
    }

    int w = tid >> 5, l = tid & 31;
    int wm = w & 3, wn = w >> 2;
    int row0 = blockIdx.x * 128;

    if (tid < 128) spath[tid] = paths[row0 + tid];
    __syncthreads();
    for (int idx = tid; idx < 128 * 25; idx += 512) {
        int r = idx / 25, k4 = idx - r * 25;
        float4 v = *(const float4*)(ent_table + (size_t)spath[r] * DENT + k4 * 4);
        uint2 u2;
        *((__half2*)&u2.x) = __floats2half2_rn(v.x, v.y);
        *((__half2*)&u2.y) = __floats2half2_rn(v.z, v.w);
        *(uint2*)(sm + SMC_A + r * CKSTR + k4 * 8) = u2;
    }
    for (int idx = tid; idx < 128 * 3; idx += 512) {
        int r = idx / 3, j = idx - r * 3;
        *(uint2*)(sm + SMC_A + r * CKSTR + 200 + j * 8) = make_uint2(0u, 0u);
    }
    for (int idx = tid; idx < 128 * 28; idx += 512) {
        int r = idx / 28, j = idx - r * 28;
        *(uint2*)(sm + SMC_B + r * CKSTR + j * 8) = ((const uint2*)g_Wec)[idx];
    }
    __syncthreads();

    uint32_t base = s2u(sm);
    int g8 = l & 7;
    uint32_t aBase = base + SMC_A + (uint32_t)(wm * 32 + g8 + ((l >> 3) & 1) * 8) * CKSTR
                   + ((l >> 4) & 1) * 16;
    uint32_t bBase = base + SMC_B + (uint32_t)(wn * 32 + g8) * CKSTR + ((l >> 3) & 1) * 16;

    float acc[2][4][4];
#pragma unroll
    for (int mt = 0; mt < 2; mt++)
#pragma unroll
        for (int nt = 0; nt < 4; nt++)
#pragma unroll
            for (int q = 0; q < 4; q++) acc[mt][nt][q] = 0.0f;

#pragma unroll
    for (int kt = 0; kt < 7; kt++) {
        uint32_t a[2][4];
        ldmA(a[0], aBase + kt * 32);
        ldmA(a[1], aBase + 16 * CKSTR + kt * 32);
#pragma unroll
        for (int nt = 0; nt < 4; nt++) {
            uint32_t b[2];
            ldmB(b, bBase + nt * 8 * CKSTR + kt * 32);
            mma16816(acc[0][nt], a[0], b);
            mma16816(acc[1][nt], a[1], b);
        }
    }
    __syncthreads();

    int tg = l & 3, gg = l >> 2;
#pragma unroll
    for (int mt = 0; mt < 2; mt++) {
        int r = wm * 32 + mt * 16 + gg;
#pragma unroll
        for (int nt = 0; nt < 4; nt++) {
            int cc = wn * 32 + nt * 8 + 2 * tg;
            float b0 = __ldg(ec_b + cc), b1 = __ldg(ec_b + cc + 1);
            *(__half2*)(sm + r * ASTR + cc * 2) =
                __floats2half2_rn(tanha(acc[mt][nt][0] + b0), tanha(acc[mt][nt][1] + b1));
            *(__half2*)(sm + (r + 8) * ASTR + cc * 2) =
                __floats2half2_rn(tanha(acc[mt][nt][2] + b0), tanha(acc[mt][nt][3] + b1));
        }
    }
    __syncthreads();
    for (int it = tid; it < 128 * 16; it += 512) {
        int r = it >> 4, bb = it & 15;
        uint4 v = *(uint4*)(sm + r * ASTR + bb * 16);
        *(uint4*)((char*)g_AE + (size_t)(row0 + r) * 256 + bb * 16) = v;
    }
}

// ---------------- L2: HMMA gate GEMM, one j-chunk per block, grid (496,4), 2 CTA/SM -------
#define SMJ_A 0
#define SMJ_B (128 * ASTR)
#define SMJ_C (2 * 128 * ASTR)
#define SMJ_TOTAL (3 * 128 * ASTR)         /* 104448 */
__global__ __launch_bounds__(512, 2) void k_gemm_mma() {
    extern __shared__ char sm[];
    int tid = threadIdx.x, w = tid >> 5, l = tid & 31;
    int wm = w & 3, wg = w >> 2;           // wg = gate
    int row0 = blockIdx.x * 128;
    int jc = blockIdx.y;

    const uint4* Ag = (const uint4*)g_AE;
    for (int idx = tid; idx < 128 * 16; idx += 512) {
        int r = idx >> 4, c4 = idx & 15;
        *(uint4*)(sm + SMJ_A + r * ASTR + c4 * 16) = Ag[(size_t)(row0 + r) * 16 + c4];
    }
    const uint4* Bg = (const uint4*)g_Bn;
    for (int idx = tid; idx < 128 * 16; idx += 512) {
        int n = idx >> 4, c4 = idx & 15;
        *(uint4*)(sm + SMJ_B + n * ASTR + c4 * 16) = Bg[(size_t)(jc * 128 + n) * 16 + c4];
    }
    __syncthreads();

    uint32_t base = s2u(sm);
    int g8 = l & 7, tg = l & 3, gg = l >> 2;
    uint32_t aBase = base + SMJ_A + (uint32_t)(wm * 32 + g8 + ((l >> 3) & 1) * 8) * ASTR
                   + ((l >> 4) & 1) * 16;
    uint32_t bBase = base + SMJ_B + (uint32_t)(wg * 32 + g8) * ASTR + ((l >> 3) & 1) * 16;

    float acc[2][4][4];
#pragma unroll
    for (int mt = 0; mt < 2; mt++)
#pragma unroll
        for (int nt = 0; nt < 4; nt++)
#pragma unroll
            for (int q = 0; q < 4; q++) acc[mt][nt][q] = 0.0f;

#pragma unroll
    for (int kt = 0; kt < 8; kt++) {
        uint32_t a[2][4];
        ldmA(a[0], aBase + kt * 32);
        ldmA(a[1], aBase + 16 * ASTR + kt * 32);
#pragma unroll
        for (int nt = 0; nt < 4; nt++) {
            uint32_t b[2];
            ldmB(b, bBase + nt * 8 * ASTR + kt * 32);
            mma16816(acc[0][nt], a[0], b);
            mma16816(acc[1][nt], a[1], b);
        }
    }
    __syncthreads();

#pragma unroll
    for (int mt = 0; mt < 2; mt++) {
        int r = wm * 32 + mt * 16 + gg;
#pragma unroll
        for (int nt = 0; nt < 4; nt++) {
            int off = (nt * 4 + tg) * 16 + wg * 4;
            *(__half2*)(sm + SMJ_C + r * ASTR + off) =
                __floats2half2_rn(acc[mt][nt][0], acc[mt][nt][1]);
            *(__half2*)(sm + SMJ_C + (r + 8) * ASTR + off) =
                __floats2half2_rn(acc[mt][nt][2], acc[mt][nt][3]);
        }
    }
    __syncthreads();
    for (int it = tid; it < 128 * 16; it += 512) {
        int r = it >> 4, q = it & 15;
        uint4 v = *(uint4*)(sm + SMJ_C + r * ASTR + q * 16);
        *(uint4*)((char*)g_G16 + (size_t)(row0 + r) * 1024 + jc * 256 + q * 16) = v;
    }
}

// ---------------- L3: barrier-free HMMA LSTM + mma MLP (f16x2 gates) ----------------------
#define SL_B  0
#define SL_W1 (512 * ASTR)                        /* 139264 */
#define SL_TOTAL (SL_W1 + 128 * ASTR)             /* 174080 */
__global__ __launch_bounds__(384, 1) void k_lstm_mma(const int* __restrict__ edges,
                                                     const float* __restrict__ mlp_b1,
                                                     const float* __restrict__ mlp_W2,
                                                     const float* __restrict__ mlp_b2,
                                                     float* __restrict__ scores_out) {
    extern __shared__ char sm[];
    int tid = threadIdx.x, w = tid >> 5, l = tid & 31;

    const uint4* Bg = (const uint4*)g_Bh;
    for (int idx = tid; idx < 512 * 16; idx += 384) {
        int n = idx >> 4, c4 = idx & 15;
        *(uint4*)(sm + SL_B + n * ASTR + c4 * 16) = Bg[(size_t)n * 16 + c4];
    }
    const uint4* Wg = (const uint4*)g_W1h;
    for (int idx = tid; idx < 128 * 16; idx += 384) {
        int n = idx >> 4, c4 = idx & 15;
        *(uint4*)(sm + SL_W1 + n * ASTR + c4 * 16) = Wg[(size_t)n * 16 + c4];
    }
    __syncthreads();

    int g8 = l & 7, t4 = l & 3, gg = l >> 2;
    int seqA = blockIdx.x * 192 + w * 16 + gg;
    if (seqA >= Nseq) return;
    int seqB = seqA + 8;
    int bA = seqA / Pn, bB = seqB / Pn;

    uint32_t base = s2u(sm);
    uint32_t bFrag = base + SL_B + (uint32_t)g8 * ASTR
                   + ((l >> 3) & 1) * 16 + ((l >> 4) & 1) * 32;
    uint32_t wFrag = base + SL_W1 + (uint32_t)g8 * ASTR
                   + ((l >> 3) & 1) * 16 + ((l >> 4) & 1) * 32;

    float cst[64];
#pragma unroll
    for (int q = 0; q < 64; q++) cst[q] = 0.0f;
    uint32_t hf[8][4];
#pragma unroll
    for (int kk = 0; kk < 8; kk++)
#pragma unroll
        for (int q = 0; q < 4; q++) hf[kk][q] = 0u;

    for (int t = 0; t < Tn; t++) {
        int rowGA = (t == 0) ? NPL + bA : (t == 4) ? NPL + Bsz + bA : seqA * Ln + (t - 1);
        int rowGB = (t == 0) ? NPL + bB : (t == 4) ? NPL + Bsz + bB : seqB * Ln + (t - 1);
        int eA = (t < Ln) ? edges[seqA * Ln + t] : 0;
        int eB = (t < Ln) ? edges[seqB * Ln + t] : 0;
        const char* gAr = (const char*)g_G16 + (size_t)rowGA * 1024 + t4 * 16;
        const char* gBr = (const char*)g_G16 + (size_t)rowGB * 1024 + t4 * 16;
        const char* rAr = (const char*)g_relGb16 + (size_t)eA * 1024 + t4 * 16;
        const char* rBr = (const char*)g_relGb16 + (size_t)eB * 1024 + t4 * 16;

        uint32_t hn[8][4];
#pragma unroll
        for (int kt = 0; kt < 8; kt++) {
#pragma unroll
            for (int half = 0; half < 2; half++) {
                int nt = kt * 2 + half;
                uint4 guA = *(const uint4*)(gAr + nt * 64);
                uint4 guB = *(const uint4*)(gBr + nt * 64);
                uint4 ruA = *(const uint4*)(rAr + nt * 64);
                uint4 ruB = *(const uint4*)(rBr + nt * 64);

                float acc[4][4];
#pragma unroll
                for (int g = 0; g < 4; g++)
#pragma unroll
                    for (int q = 0; q < 4; q++) acc[g][q] = 0.0f;
                if (t > 0) {
                    uint32_t tRow = (uint32_t)(nt * 8) * ASTR;
#pragma unroll
                    for (int kp = 0; kp < 4; kp++) {
#pragma unroll
                        for (int g = 0; g < 4; g++) {
                            uint32_t b4[4];
                            ldmB4(b4, bFrag + tRow + (uint32_t)(g * 128) * ASTR + kp * 64);
                            mma16816(acc[g], hf[2 * kp], b4);
                            mma16816(acc[g], hf[2 * kp + 1], b4 + 2);
                        }
                    }
                }
                int ci = nt * 4;
                // ---- row A (f16x2 gate math) ----
                __half2 gI = __hadd2(__hadd2(*(const __half2*)&guA.x, *(const __half2*)&ruA.x),
                                     __floats2half2_rn(acc[0][0], acc[0][1]));
                __half2 gF = __hadd2(__hadd2(*(const __half2*)&guA.y, *(const __half2*)&ruA.y),
                                     __floats2half2_rn(acc[1][0], acc[1][1]));
                __half2 gG = __hadd2(__hadd2(*(const __half2*)&guA.z, *(const __half2*)&ruA.z),
                                     __floats2half2_rn(acc[2][0], acc[2][1]));
                __half2 gO = __hadd2(__hadd2(*(const __half2*)&guA.w, *(const __half2*)&ruA.w),
                                     __floats2half2_rn(acc[3][0], acc[3][1]));
                __half2 si = sig2(gI), sf = sig2(gF), tg2 = tanh2(gG), so = sig2(gO);
                float2 fi = __half22float2(si), ff = __half22float2(sf), fg = __half22float2(tg2);
                cst[ci]     = ff.x * cst[ci]     + fi.x * fg.x;
                cst[ci + 1] = ff.y * cst[ci + 1] + fi.y * fg.y;
                __half2 pA = __hmul2(so, tanh2(__floats2half2_rn(cst[ci], cst[ci + 1])));
                // ---- row B ----
                gI = __hadd2(__hadd2(*(const __half2*)&guB.x, *(const __half2*)&ruB.x),
                             __floats2half2_rn(acc[0][2], acc[0][3]));
                gF = __hadd2(__hadd2(*(const __half2*)&guB.y, *(const __half2*)&ruB.y),
                             __floats2half2_rn(acc[1][2], acc[1][3]));
                gG = __hadd2(__hadd2(*(const __half2*)&guB.z, *(const __half2*)&ruB.z),
                             __floats2half2_rn(acc[2][2], acc[2][3]));
                gO = __hadd2(__hadd2(*(const __half2*)&guB.w, *(const __half2*)&ruB.w),
                             __floats2half2_rn(acc[3][2], acc[3][3]));
                si = sig2(gI); sf = sig2(gF); tg2 = tanh2(gG); so = sig2(gO);
                fi = __half22float2(si); ff = __half22float2(sf); fg = __half22float2(tg2);
                cst[ci + 2] = ff.x * cst[ci + 2] + fi.x * fg.x;
                cst[ci + 3] = ff.y * cst[ci + 3] + fi.y * fg.y;
                __half2 pB = __hmul2(so, tanh2(__floats2half2_rn(cst[ci + 2], cst[ci + 3])));

                hn[kt][half * 2]     = *(uint32_t*)&pA;
                hn[kt][half * 2 + 1] = *(uint32_t*)&pB;
            }
        }
#pragma unroll
        for (int kk = 0; kk < 8; kk++)
#pragma unroll
            for (int q = 0; q < 4; q++) hf[kk][q] = hn[kk][q];
    }

    // ---- MLP via mma on register h-fragments ----
    float sc0 = 0.0f, sc1 = 0.0f;
#pragma unroll
    for (int ntg = 0; ntg < 16; ntg++) {
        float acc[4];
#pragma unroll
        for (int q = 0; q < 4; q++) acc[q] = 0.0f;
        uint32_t tRow = (uint32_t)(ntg * 8) * ASTR;
#pragma unroll
        for (int kp = 0; kp < 4; kp++) {
            uint32_t b4[4];
            ldmB4(b4, wFrag + tRow + kp * 64);
            mma16816(acc, hf[2 * kp], b4);
            mma16816(acc, hf[2 * kp + 1], b4 + 2);
        }
        int j0 = ntg * 8 + t4 * 2;
        float b10 = __ldg(mlp_b1 + j0), b11 = __ldg(mlp_b1 + j0 + 1);
        float w20 = __ldg(mlp_W2 + j0), w21 = __ldg(mlp_W2 + j0 + 1);
        sc0 += fmaxf(acc[0] + b10, 0.0f) * w20 + fmaxf(acc[1] + b11, 0.0f) * w21;
        sc1 += fmaxf(acc[2] + b10, 0.0f) * w20 + fmaxf(acc[3] + b11, 0.0f) * w21;
    }
    sc0 += __shfl_xor_sync(0xffffffffu, sc0, 1);
    sc0 += __shfl_xor_sync(0xffffffffu, sc0, 2);
    sc1 += __shfl_xor_sync(0xffffffffu, sc1, 1);
    sc1 += __shfl_xor_sync(0xffffffffu, sc1, 2);
    if (t4 == 0) {
        float b2 = __ldg(mlp_b2);
        scores_out[seqA] = sc0 + b2;
        scores_out[seqB] = sc1 + b2;
    }
}

// ---------------- L4: logsumexp + BCE ----------------
__global__ void k_final(const float* __restrict__ label, float* __restrict__ out) {
    __shared__ float red[Bsz];
    int b = threadIdx.x;
    const float* sc = out + 1 + Bsz + b * Pn;
    float mx = -1e30f;
#pragma unroll
    for (int p = 0; p < Pn; p++) mx = fmaxf(mx, sc[p] * 0.5f);
    float s = 0.0f;
#pragma unroll
    for (int p = 0; p < Pn; p++) s += expf(sc[p] * 0.5f - mx);
    float lse = mx + logf(s);
    float pr = 1.0f / (1.0f + expf(-lse));
    out[1 + b] = pr;
    float pc = fminf(fmaxf(pr, 1e-7f), 1.0f - 1e-7f);
    float lb = label[b];
    red[b] = -(lb * logf(pc) + (1.0f - lb) * logf(1.0f - pc));
    __syncthreads();
    for (int st = Bsz / 2; st > 0; st >>= 1) {
        if (b < st) red[b] += red[b + st];
        __syncthreads();
    }
    if (b == 0) out[0] = red[0] / (float)Bsz;
}

// ---------------- launch ----------------
extern "C" void kernel_launch(void* const* d_in, const int* in_sizes, int n_in,
                              void* d_out, int out_size) {
    const int*   item1     = (const int*)d_in[0];
    const int*   item2     = (const int*)d_in[1];
    const int*   paths     = (const int*)d_in[2];
    const int*   edges     = (const int*)d_in[3];
    const float* label     = (const float*)d_in[4];
    const float* doc_table = (const float*)d_in[5];
    const float* ent_table = (const float*)d_in[6];
    const float* rel_table = (const float*)d_in[7];
    const float* nc_W1 = (const float*)d_in[8];
    const float* nc_b1 = (const float*)d_in[9];
    const float* nc_W2 = (const float*)d_in[10];
    const float* nc_b2 = (const float*)d_in[11];
    const float* ec_W  = (const float*)d_in[12];
    const float* ec_b  = (const float*)d_in[13];
    const float* rc_W  = (const float*)d_in[14];
    const float* rc_b  = (const float*)d_in[15];
    const float* W_ih  = (const float*)d_in[16];
    const float* W_hh  = (const float*)d_in[17];
    const float* b_ih  = (const float*)d_in[18];
    const float* b_hh  = (const float*)d_in[19];
    const float* mlp_W1 = (const float*)d_in[20];
    const float* mlp_b1 = (const float*)d_in[21];
    const float* mlp_W2 = (const float*)d_in[22];
    const float* mlp_b2 = (const float*)d_in[23];
    float* out = (float*)d_out;

    cudaFuncSetAttribute(k_compress_rel, cudaFuncAttributeMaxDynamicSharedMemorySize, SMC_TOTAL);
    cudaFuncSetAttribute(k_gemm_mma, cudaFuncAttributeMaxDynamicSharedMemorySize, SMJ_TOTAL);
    cudaFuncSetAttribute(k_lstm_mma, cudaFuncAttributeMaxDynamicSharedMemorySize, SL_TOTAL);

    k_news_transpose<<<768, 128>>>(item1, item2, doc_table, nc_W1, nc_b1, nc_W2, nc_b2,
                                   W_ih, W_hh, ec_W, mlp_W1);
    k_compress_rel<<<NPL / 128 + NREL, 512, SMC_TOTAL>>>(paths, ent_table, ec_b,
                                                         rel_table, rc_W, rc_b, b_ih, b_hh);
    k_gemm_mma<<<dim3(MTOT / 128, 4), 512, SMJ_TOTAL>>>();
    k_lstm_mma<<<(Nseq + 191) / 192, 384, SL_TOTAL>>>(edges, mlp_b1, mlp_W2, mlp_b2,
                                                      out + 1 + Bsz);
    k_final<<<1, Bsz>>>(label, out);
}